// round 13
// baseline (speedup 1.0000x reference)
#include <cuda_runtime.h>
#include <cuda_bf16.h>
#include <math.h>
#include <cstdint>

#define SEQ 4096
#define DMODEL 1024
#define NHEAD 16
#define DK 64

// ---------------------------------------------------------------------------
// Scratch (device globals — no runtime allocation allowed)
// ---------------------------------------------------------------------------
__device__ __align__(16) __nv_bfloat16 g_xhi[SEQ * DMODEL];
__device__ __align__(16) __nv_bfloat16 g_xlo[SEQ * DMODEL];
__device__ __align__(16) __nv_bfloat16 g_whi[4 * DMODEL * DMODEL];
__device__ __align__(16) __nv_bfloat16 g_wlo[4 * DMODEL * DMODEL];
__device__ __align__(16) __nv_bfloat16 g_chi[SEQ * DMODEL];
__device__ __align__(16) __nv_bfloat16 g_clo[SEQ * DMODEL];

__device__ __align__(16) __nv_bfloat16 g_qhi[SEQ * DMODEL];
__device__ __align__(16) __nv_bfloat16 g_qlo[SEQ * DMODEL];
__device__ __align__(16) __nv_bfloat16 g_khi[SEQ * DMODEL];
__device__ __align__(16) __nv_bfloat16 g_klo[SEQ * DMODEL];
__device__ __align__(16) __nv_bfloat16 g_vhi[SEQ * DMODEL];
__device__ __align__(16) __nv_bfloat16 g_vlo[SEQ * DMODEL];

// rope cos/sin table: [pos][freq] -> (cos, sin), 4096 x 32 float2 = 1 MB
__device__ __align__(16) float2 g_ropetab[SEQ * 32];

// work-stealing counter for the persistent attention kernel (reset per launch)
__device__ int g_attn_work;

// ---------------------------------------------------------------------------
// Baseline-PTX helpers
// ---------------------------------------------------------------------------
__device__ __forceinline__ uint32_t smem_u32(const void* p) {
    uint32_t a;
    asm("{ .reg .u64 t; cvta.to.shared.u64 t, %1; cvt.u32.u64 %0, t; }"
        : "=r"(a) : "l"(p));
    return a;
}

__device__ __forceinline__ void cp16(uint32_t dst, const void* src) {
    asm volatile("cp.async.cg.shared.global [%0], [%1], 16;"
        :: "r"(dst), "l"(src) : "memory");
}
#define CP_COMMIT() asm volatile("cp.async.commit_group;" ::: "memory")
#define CP_WAIT1()  asm volatile("cp.async.wait_group 1;" ::: "memory")
#define CP_WAIT0()  asm volatile("cp.async.wait_group 0;" ::: "memory")

__device__ __forceinline__ void ldsm4(uint32_t r[4], uint32_t addr) {
    asm volatile("ldmatrix.sync.aligned.m8n8.x4.shared.b16 {%0,%1,%2,%3}, [%4];"
        : "=r"(r[0]), "=r"(r[1]), "=r"(r[2]), "=r"(r[3]) : "r"(addr));
}
__device__ __forceinline__ void ldsm4t(uint32_t r[4], uint32_t addr) {
    asm volatile("ldmatrix.sync.aligned.m8n8.x4.trans.shared.b16 {%0,%1,%2,%3}, [%4];"
        : "=r"(r[0]), "=r"(r[1]), "=r"(r[2]), "=r"(r[3]) : "r"(addr));
}

__device__ __forceinline__ void mma_bf16(float c[4], const uint32_t a[4],
                                         uint32_t b0, uint32_t b1) {
    asm volatile(
        "mma.sync.aligned.m16n8k16.row.col.f32.bf16.bf16.f32 "
        "{%0,%1,%2,%3}, {%4,%5,%6,%7}, {%8,%9}, {%0,%1,%2,%3};"
        : "+f"(c[0]), "+f"(c[1]), "+f"(c[2]), "+f"(c[3])
        : "r"(a[0]), "r"(a[1]), "r"(a[2]), "r"(a[3]), "r"(b0), "r"(b1));
}

__device__ __forceinline__ void split2(float a, float b, uint32_t& hi, uint32_t& lo) {
    __nv_bfloat16 ha = __float2bfloat16(a);
    __nv_bfloat16 hb = __float2bfloat16(b);
    __nv_bfloat162 hp(ha, hb);
    __nv_bfloat162 lp(__float2bfloat16(a - __bfloat162float(ha)),
                      __float2bfloat16(b - __bfloat162float(hb)));
    hi = *(uint32_t*)&hp;
    lo = *(uint32_t*)&lp;
}

// ---------------------------------------------------------------------------
// rope table: angle(pos, i) = pos * 10000^(-i/32)
// ---------------------------------------------------------------------------
__global__ void rope_table()
{
    int idx = blockIdx.x * blockDim.x + threadIdx.x;
    if (idx >= SEQ * 32) return;
    const int pos = idx >> 5;
    const int i   = idx & 31;
    const float c1 = -9.210340371976184f / 32.0f;   // -ln(10000)/32
    const float ang = (float)pos * expf((float)i * c1);
    float sn, cs;
    sincosf(ang, &sn, &cs);
    g_ropetab[idx] = make_float2(cs, sn);
}

// ---------------------------------------------------------------------------
// Split x + the 4 weights into bf16 hi/lo.
// grid.y (8 slices of 256K float4 each):
//   0..3 -> quarters of x (SEQ*DMODEL = 4 * DMODEL*DMODEL floats)
//   4..7 -> Wq, Wk, Wv, Wo
// ---------------------------------------------------------------------------
#define WQ4 (DMODEL * DMODEL / 4)   // 256K float4 per weight / per x-quarter

__global__ void split_all(const float* __restrict__ x,
                          const float* __restrict__ w0, const float* __restrict__ w1,
                          const float* __restrict__ w2, const float* __restrict__ w3,
                          __nv_bfloat16* __restrict__ xhi, __nv_bfloat16* __restrict__ xlo,
                          __nv_bfloat16* __restrict__ whi, __nv_bfloat16* __restrict__ wlo)
{
    const int sel = blockIdx.y;
    int i = blockIdx.x * blockDim.x + threadIdx.x;
    if (i >= WQ4) return;

    const float* src;
    __nv_bfloat16 *hi, *lo;
    size_t base;
    if (sel < 4) {                       // quarter 'sel' of x
        src = x + (size_t)sel * WQ4 * 4;
        hi = xhi; lo = xlo;
        base = (size_t)sel * WQ4;
    } else {
        src = (sel == 4) ? w0 : (sel == 5) ? w1 : (sel == 6) ? w2 : w3;
        hi = whi; lo = wlo;
        base = (size_t)(sel - 4) * WQ4;
    }

    float4 v = ((const float4*)src)[i];
    uint32_t h0, l0, h1, l1;
    split2(v.x, v.y, h0, l0);
    split2(v.z, v.w, h1, l1);
    ((uint2*)hi)[base + i] = make_uint2(h0, h1);
    ((uint2*)lo)[base + i] = make_uint2(l0, l1);
}

// ---------------------------------------------------------------------------
// Tensor-core GEMM: 128x128 CTA tile, 4 warps (2x2), 64x64 warp tile.
// BK=32, TWO-stage cp.async pipeline. hi/lo split, fp32 accum.
// ---------------------------------------------------------------------------
#define BK 32
#define NT (DMODEL / BK)
#define TILE_B (128 * 64)           // 8 KB per operand tile
#define STAGE_B (4 * TILE_B)        // 32 KB

struct GemmCore {
    float acc[4][8][4];
    int r0, c0;
};

__device__ __forceinline__ void gemm_mainloop(
    const __nv_bfloat16* __restrict__ Ahi, const __nv_bfloat16* __restrict__ Alo,
    const __nv_bfloat16* __restrict__ Bhi, const __nv_bfloat16* __restrict__ Blo,
    int bm, int bn, char* smem, GemmCore& core)
{
    const int tid  = threadIdx.x;
    const int wid  = tid >> 5, lane = tid & 31;
    const int wm   = wid & 1;
    const int wn   = wid >> 1;
    const uint32_t sbase = smem_u32(smem);

    const __nv_bfloat16* srcs[4] = {
        Ahi + (size_t)bm * DMODEL, Alo + (size_t)bm * DMODEL,
        Bhi + (size_t)bn * DMODEL, Blo + (size_t)bn * DMODEL };

    auto copy_stage = [&](int s, int k0) {
        const uint32_t stb = sbase + s * STAGE_B;
#pragma unroll
        for (int t = 0; t < 4; t++) {
            const __nv_bfloat16* base = srcs[t];
#pragma unroll
            for (int j = 0; j < 4; j++) {
                const int idx = j * 128 + tid;
                const int r = idx >> 2, c = idx & 3;
                const uint32_t pc = (uint32_t)(c ^ ((r >> 1) & 3));
                cp16(stb + t * TILE_B + (uint32_t)r * 64 + pc * 16,
                     base + (size_t)r * DMODEL + k0 + c * 8);
            }
        }
    };

    const int arow = wm * 64 + (lane & 15);
    const int ac0  = lane >> 4;
    const uint32_t aoff = (uint32_t)arow * 64 +
                          (uint32_t)((ac0 ^ ((arow >> 1) & 3)) * 16);
    const int brow = wn * 64 + ((lane >> 4) << 3) + (lane & 7);
    const int bc0  = (lane >> 3) & 1;
    const uint32_t boff = (uint32_t)brow * 64 +
                          (uint32_t)((bc0 ^ ((brow >> 1) & 3)) * 16);

#pragma unroll
    for (int i = 0; i < 4; i++)
#pragma unroll
        for (int j = 0; j < 8; j++)
#pragma unroll
            for (int q = 0; q < 4; q++) core.acc[i][j][q] = 0.f;

    copy_stage(0, 0);
    CP_COMMIT();

    for (int kt = 0; kt < NT; kt++) {
        const int s = kt & 1;
        if (kt + 1 < NT) {
            copy_stage(s ^ 1, (kt + 1) * BK);
            CP_COMMIT();
            CP_WAIT1();
        } else {
            CP_WAIT0();
        }
        __syncthreads();

        const uint32_t stb  = sbase + s * STAGE_B;
        const uint32_t sAhi = stb + aoff;
        const uint32_t sAlo = stb + TILE_B + aoff;
        const uint32_t sBhi = stb + 2 * TILE_B + boff;
        const uint32_t sBlo = stb + 3 * TILE_B + boff;

#pragma unroll
        for (int ks = 0; ks < 2; ks++) {
            const uint32_t kx = (uint32_t)(ks << 5);
            uint32_t ah[4][4], al[4][4], bh[4][4], bl[4][4];
#pragma unroll
            for (int mf = 0; mf < 4; mf++) {
                ldsm4(ah[mf], (sAhi + mf * 1024) ^ kx);
                ldsm4(al[mf], (sAlo + mf * 1024) ^ kx);
            }
#pragma unroll
            for (int np = 0; np < 4; np++) {
                ldsm4(bh[np], (sBhi + np * 1024) ^ kx);
                ldsm4(bl[np], (sBlo + np * 1024) ^ kx);
            }
#pragma unroll
            for (int mf = 0; mf < 4; mf++) {
#pragma unroll
                for (int nt = 0; nt < 8; nt++) {
                    const int np = nt >> 1, hh = (nt & 1) * 2;
                    mma_bf16(core.acc[mf][nt], ah[mf], bh[np][hh], bh[np][hh + 1]);
                    mma_bf16(core.acc[mf][nt], ah[mf], bl[np][hh], bl[np][hh + 1]);
                    mma_bf16(core.acc[mf][nt], al[mf], bh[np][hh], bh[np][hh + 1]);
                }
            }
        }
        __syncthreads();
    }

    core.r0 = bm + wm * 64 + (lane >> 2);
    core.c0 = bn + wn * 64 + (lane & 3) * 2;
}

// Fused QKV projection. z=0/1: rope (via table) + scale + split epilogue
// into q/k hi+lo. z=2: plain split into v hi+lo.
__global__ __launch_bounds__(128, 2) void gemm_qkv(
    const __nv_bfloat16* __restrict__ Xhi, const __nv_bfloat16* __restrict__ Xlo,
    const __nv_bfloat16* __restrict__ Whi, const __nv_bfloat16* __restrict__ Wlo,
    __nv_bfloat16* __restrict__ Qhi, __nv_bfloat16* __restrict__ Qlo,
    __nv_bfloat16* __restrict__ Khi, __nv_bfloat16* __restrict__ Klo,
    __nv_bfloat16* __restrict__ Vhi, __nv_bfloat16* __restrict__ Vlo)
{
    extern __shared__ __align__(1024) char smem[];
    const int z = blockIdx.z;
    const size_t woff = (size_t)z * DMODEL * DMODEL;

    GemmCore core;
    gemm_mainloop(Xhi, Xlo, Whi + woff, Wlo + woff,
                  blockIdx.y * 128, blockIdx.x * 128, smem, core);

    if (z == 2) {
#pragma unroll
        for (int mf = 0; mf < 4; mf++) {
#pragma unroll
            for (int nt = 0; nt < 8; nt++) {
                const size_t o0 = (size_t)(core.r0 + mf * 16) * DMODEL + core.c0 + nt * 8;
                const size_t o1 = (size_t)(core.r0 + mf * 16 + 8) * DMODEL + core.c0 + nt * 8;
                uint32_t h, l;
                split2(core.acc[mf][nt][0], core.acc[mf][nt][1], h, l);
                *(uint32_t*)&Vhi[o0] = h; *(uint32_t*)&Vlo[o0] = l;
                split2(core.acc[mf][nt][2], core.acc[mf][nt][3], h, l);
                *(uint32_t*)&Vhi[o1] = h; *(uint32_t*)&Vlo[o1] = l;
            }
        }
    } else {
        __nv_bfloat16* Hi = (z == 0) ? Qhi : Khi;
        __nv_bfloat16* Lo = (z == 0) ? Qlo : Klo;
        const float scale = (z == 0) ? 0.125f : 1.0f;
#pragma unroll
        for (int nt = 0; nt < 8; nt++) {
            const int col  = core.c0 + nt * 8;       // even; (col,col+1) is a rope pair
            const int freq = (col & 63) >> 1;
#pragma unroll
            for (int mf = 0; mf < 4; mf++) {
                const int row0 = core.r0 + mf * 16;
                float2 t0 = g_ropetab[row0 * 32 + freq];
                float x1 = core.acc[mf][nt][0], x2 = core.acc[mf][nt][1];
                uint32_t h, l;
                split2((x1 * t0.x - x2 * t0.y) * scale,
                       (x1 * t0.y + x2 * t0.x) * scale, h, l);
                const size_t o0 = (size_t)row0 * DMODEL + col;
                *(uint32_t*)&Hi[o0] = h; *(uint32_t*)&Lo[o0] = l;

                const int row1 = row0 + 8;
                float2 t1 = g_ropetab[row1 * 32 + freq];
                x1 = core.acc[mf][nt][2]; x2 = core.acc[mf][nt][3];
                split2((x1 * t1.x - x2 * t1.y) * scale,
                       (x1 * t1.y + x2 * t1.x) * scale, h, l);
                const size_t o1 = (size_t)row1 * DMODEL + col;
                *(uint32_t*)&Hi[o1] = h; *(uint32_t*)&Lo[o1] = l;
            }
        }
    }
}

__global__ __launch_bounds__(128, 2) void gemm_tc(
    const __nv_bfloat16* __restrict__ Ahi, const __nv_bfloat16* __restrict__ Alo,
    const __nv_bfloat16* __restrict__ Bhi, const __nv_bfloat16* __restrict__ Blo,
    float* __restrict__ C)
{
    extern __shared__ __align__(1024) char smem[];
    GemmCore core;
    gemm_mainloop(Ahi, Alo, Bhi, Blo, blockIdx.y * 128, blockIdx.x * 128, smem, core);
#pragma unroll
    for (int mf = 0; mf < 4; mf++) {
#pragma unroll
        for (int nt = 0; nt < 8; nt++) {
            float* p0 = &C[(size_t)(core.r0 + mf * 16) * DMODEL + core.c0 + nt * 8];
            float* p1 = &C[(size_t)(core.r0 + mf * 16 + 8) * DMODEL + core.c0 + nt * 8];
            *(float2*)p0 = make_float2(core.acc[mf][nt][0], core.acc[mf][nt][1]);
            *(float2*)p1 = make_float2(core.acc[mf][nt][2], core.acc[mf][nt][3]);
        }
    }
}

// ---------------------------------------------------------------------------
// PERSISTENT tensor-core causal flash attention (unchanged from 559us build)
// ---------------------------------------------------------------------------
#define ATT_TILE_B 8192
#define ATT_STAGE_B (4 * ATT_TILE_B)
#define ATT_SMEM (32768 + 2 * ATT_STAGE_B)   // 96 KB
#define ATT_UNITS (32 * NHEAD)               // 512
#define ATT_CTAS 296                         // 2 per SM x 148 SMs

__global__ __launch_bounds__(128, 2) void attn_tc(
    const __nv_bfloat16* __restrict__ Qhi, const __nv_bfloat16* __restrict__ Qlo,
    const __nv_bfloat16* __restrict__ Khi, const __nv_bfloat16* __restrict__ Klo,
    const __nv_bfloat16* __restrict__ Vhi, const __nv_bfloat16* __restrict__ Vlo,
    __nv_bfloat16* __restrict__ Chi, __nv_bfloat16* __restrict__ Clo)
{
    extern __shared__ __align__(1024) char smem[];
    __shared__ int s_unit;
    const uint32_t sb = smem_u32(smem);
    const uint32_t qhib = sb, qlob = sb + 16384;
    const uint32_t stgb = sb + 32768;

    const int tid  = threadIdx.x;
    const int wid  = tid >> 5, lane = tid & 31;

    const uint32_t lx = (uint32_t)(lane & 7);
    uint32_t qoff[4], koff[4], voff[4];
#pragma unroll
    for (int ks = 0; ks < 4; ks++) {
        qoff[ks] = (uint32_t)(lane & 15) * 128 +
                   ((uint32_t)(ks * 2 + (lane >> 4)) ^ lx) * 16;
        koff[ks] = (uint32_t)(((lane >> 4) << 3) + (lane & 7)) * 128 +
                   ((uint32_t)(ks * 2 + ((lane >> 3) & 1)) ^ lx) * 16;
        voff[ks] = (uint32_t)(lane & 15) * 128 +
                   ((uint32_t)(ks * 2 + (lane >> 4)) ^ lx) * 16;
    }

    for (;;) {
        __syncthreads();
        if (tid == 0) s_unit = atomicAdd(&g_attn_work, 1);
        __syncthreads();
        const int u = s_unit;
        if (u >= ATT_UNITS) break;

        const int qtile = 31 - (u >> 4);     // LPT: largest tiles first
        const int h     = u & 15;
        const int hcol  = h * DK;
        const int q0 = qtile * 128;
        const int ntiles = qtile * 2 + 2;

#pragma unroll
        for (int j = 0; j < 8; j++) {
            const int idx = j * 128 + tid;
            const int r = idx >> 3, c = idx & 7;
            const uint32_t off = (uint32_t)r * 128 + ((uint32_t)c ^ (uint32_t)(r & 7)) * 16;
            const size_t g = (size_t)(q0 + r) * DMODEL + hcol + c * 8;
            cp16(qhib + off, Qhi + g);
            cp16(qlob + off, Qlo + g);
        }
        CP_COMMIT();

        {
            const uint32_t stb = stgb;
#pragma unroll
            for (int j = 0; j < 4; j++) {
                const int idx = j * 128 + tid;
                const int r = idx >> 3, c = idx & 7;
                const uint32_t off = (uint32_t)r * 128 + ((uint32_t)c ^ (uint32_t)(r & 7)) * 16;
                const size_t g = (size_t)r * DMODEL + hcol + c * 8;
                cp16(stb + off,                  Khi + g);
                cp16(stb + ATT_TILE_B + off,     Klo + g);
                cp16(stb + 2 * ATT_TILE_B + off, Vhi + g);
                cp16(stb + 3 * ATT_TILE_B + off, Vlo + g);
            }
        }
        CP_COMMIT();

        CP_WAIT1();
        __syncthreads();

        uint32_t qh[2][4][4], ql[2][4][4];
        const uint32_t qrb = (uint32_t)(wid * 32) * 128;
#pragma unroll
        for (int mf = 0; mf < 2; mf++)
#pragma unroll
            for (int ks = 0; ks < 4; ks++) {
                ldsm4(qh[mf][ks], qhib + qrb + mf * 2048 + qoff[ks]);
                ldsm4(ql[mf][ks], qlob + qrb + mf * 2048 + qoff[ks]);
            }

        float O[2][8][4];
#pragma unroll
        for (int mf = 0; mf < 2; mf++)
#pragma unroll
            for (int f = 0; f < 8; f++)
#pragma unroll
                for (int q = 0; q < 4; q++) O[mf][f][q] = 0.f;
        float l0[2] = {0.f, 0.f}, l1[2] = {0.f, 0.f};

        int r0g[2], r1g[2];
#pragma unroll
        for (int mf = 0; mf < 2; mf++) {
            r0g[mf] = q0 + wid * 32 + mf * 16 + (lane >> 2);
            r1g[mf] = r0g[mf] + 8;
        }
        const int wrow_min = q0 + wid * 32;
        const int wrow_max = wrow_min + 31;

        for (int t = 0; t < ntiles; t++) {
            const int s = t & 1;
            if (t + 1 < ntiles) {
                const uint32_t stb = stgb + (s ^ 1) * ATT_STAGE_B;
                const int kn0 = (t + 1) * 64;
#pragma unroll
                for (int j = 0; j < 4; j++) {
                    const int idx = j * 128 + tid;
                    const int r = idx >> 3, c = idx & 7;
                    const uint32_t off = (uint32_t)r * 128 + ((uint32_t)c ^ (uint32_t)(r & 7)) * 16;
                    const size_t g = (size_t)(kn0 + r) * DMODEL + hcol + c * 8;
                    cp16(stb + off,                  Khi + g);
                    cp16(stb + ATT_TILE_B + off,     Klo + g);
                    cp16(stb + 2 * ATT_TILE_B + off, Vhi + g);
                    cp16(stb + 3 * ATT_TILE_B + off, Vlo + g);
                }
                CP_COMMIT();
                CP_WAIT1();
            } else {
                CP_WAIT0();
            }
            __syncthreads();

            const int k0 = t * 64;
            if (wrow_max >= k0) {
                const bool nomask = (k0 + 63) <= wrow_min;
                const uint32_t stb = stgb + s * ATT_STAGE_B;

#pragma unroll
                for (int np = 0; np < 4; np++) {
                    if (k0 + np * 16 > wrow_max) continue;   // P would be exactly 0

                    float s8[2][8];
#pragma unroll
                    for (int mf = 0; mf < 2; mf++)
#pragma unroll
                        for (int e = 0; e < 8; e++) s8[mf][e] = 0.f;
#pragma unroll
                    for (int ks = 0; ks < 4; ks++) {
                        uint32_t kh[4], kl[4];
                        const uint32_t ka = stb + (uint32_t)np * 2048 + koff[ks];
                        ldsm4(kh, ka);
                        ldsm4(kl, ka + ATT_TILE_B);
#pragma unroll
                        for (int mf = 0; mf < 2; mf++) {
                            mma_bf16(&s8[mf][0], qh[mf][ks], kh[0], kh[1]);
                            mma_bf16(&s8[mf][0], qh[mf][ks], kl[0], kl[1]);
                            mma_bf16(&s8[mf][0], ql[mf][ks], kh[0], kh[1]);
                            mma_bf16(&s8[mf][4], qh[mf][ks], kh[2], kh[3]);
                            mma_bf16(&s8[mf][4], qh[mf][ks], kl[2], kl[3]);
                            mma_bf16(&s8[mf][4], ql[mf][ks], kh[2], kh[3]);
                        }
                    }

                    const int c0 = k0 + np * 16 + ((lane & 3) << 1);
                    uint32_t Ph[2][4], Pl[2][4];
#pragma unroll
                    for (int mf = 0; mf < 2; mf++) {
                        float p[8];
                        if (nomask) {
#pragma unroll
                            for (int e = 0; e < 8; e++) p[e] = __expf(s8[mf][e]);
                        } else {
                            p[0] = (c0     <= r0g[mf]) ? __expf(s8[mf][0]) : 0.f;
                            p[1] = (c0 + 1 <= r0g[mf]) ? __expf(s8[mf][1]) : 0.f;
                            p[2] = (c0     <= r1g[mf]) ? __expf(s8[mf][2]) : 0.f;
                            p[3] = (c0 + 1 <= r1g[mf]) ? __expf(s8[mf][3]) : 0.f;
                            p[4] = (c0 + 8 <= r0g[mf]) ? __expf(s8[mf][4]) : 0.f;
                            p[5] = (c0 + 9 <= r0g[mf]) ? __expf(s8[mf][5]) : 0.f;
                            p[6] = (c0 + 8 <= r1g[mf]) ? __expf(s8[mf][6]) : 0.f;
                            p[7] = (c0 + 9 <= r1g[mf]) ? __expf(s8[mf][7]) : 0.f;
                        }
                        l0[mf] += (p[0] + p[1]) + (p[4] + p[5]);
                        l1[mf] += (p[2] + p[3]) + (p[6] + p[7]);
#pragma unroll
                        for (int j = 0; j < 4; j++)
                            split2(p[2 * j], p[2 * j + 1], Ph[mf][j], Pl[mf][j]);
                    }

#pragma unroll
                    for (int dn = 0; dn < 4; dn++) {
                        uint32_t vh[4], vl[4];
                        const uint32_t va = stb + (uint32_t)np * 2048 + voff[dn];
                        ldsm4t(vh, va + 2 * ATT_TILE_B);
                        ldsm4t(vl, va + 3 * ATT_TILE_B);
#pragma unroll
                        for (int mf = 0; mf < 2; mf++) {
                            mma_bf16(O[mf][dn * 2],     Ph[mf], vh[0], vh[1]);
                            mma_bf16(O[mf][dn * 2 + 1], Ph[mf], vh[2], vh[3]);
                            mma_bf16(O[mf][dn * 2],     Ph[mf], vl[0], vl[1]);
                            mma_bf16(O[mf][dn * 2 + 1], Ph[mf], vl[2], vl[3]);
                            mma_bf16(O[mf][dn * 2],     Pl[mf], vh[0], vh[1]);
                            mma_bf16(O[mf][dn * 2 + 1], Pl[mf], vh[2], vh[3]);
                        }
                    }
                }
            }
            __syncthreads();
        }

        const int cbase = hcol + ((lane & 3) << 1);
#pragma unroll
        for (int mf = 0; mf < 2; mf++) {
            float a0 = l0[mf], a1 = l1[mf];
            a0 += __shfl_xor_sync(0xFFFFFFFF, a0, 1);
            a0 += __shfl_xor_sync(0xFFFFFFFF, a0, 2);
            a1 += __shfl_xor_sync(0xFFFFFFFF, a1, 1);
            a1 += __shfl_xor_sync(0xFFFFFFFF, a1, 2);
            const float inv0 = 1.f / a0, inv1 = 1.f / a1;
#pragma unroll
            for (int f = 0; f < 8; f++) {
                const size_t o0 = (size_t)r0g[mf] * DMODEL + cbase + f * 8;
                const size_t o1 = (size_t)r1g[mf] * DMODEL + cbase + f * 8;
                uint32_t hh, ll;
                split2(O[mf][f][0] * inv0, O[mf][f][1] * inv0, hh, ll);
                *(uint32_t*)&Chi[o0] = hh; *(uint32_t*)&Clo[o0] = ll;
                split2(O[mf][f][2] * inv1, O[mf][f][3] * inv1, hh, ll);
                *(uint32_t*)&Chi[o1] = hh; *(uint32_t*)&Clo[o1] = ll;
            }
        }
    }
}

// ---------------------------------------------------------------------------
extern "C" void kernel_launch(void* const* d_in, const int* in_sizes, int n_in,
                              void* d_out, int out_size)
{
    const float* x  = (const float*)d_in[0];
    const float* Wq = (const float*)d_in[1];
    const float* Wk = (const float*)d_in[2];
    const float* Wv = (const float*)d_in[3];
    const float* Wo = (const float*)d_in[4];
    float* out = (float*)d_out;

    __nv_bfloat16 *xhi, *xlo, *whi, *wlo, *chi, *clo;
    cudaGetSymbolAddress((void**)&xhi, g_xhi);
    cudaGetSymbolAddress((void**)&xlo, g_xlo);
    cudaGetSymbolAddress((void**)&whi, g_whi);
    cudaGetSymbolAddress((void**)&wlo, g_wlo);
    cudaGetSymbolAddress((void**)&chi, g_chi);
    cudaGetSymbolAddress((void**)&clo, g_clo);

    __nv_bfloat16 *qhi, *qlo, *khi, *klo, *vhi, *vlo;
    cudaGetSymbolAddress((void**)&qhi, g_qhi);
    cudaGetSymbolAddress((void**)&qlo, g_qlo);
    cudaGetSymbolAddress((void**)&khi, g_khi);
    cudaGetSymbolAddress((void**)&klo, g_klo);
    cudaGetSymbolAddress((void**)&vhi, g_vhi);
    cudaGetSymbolAddress((void**)&vlo, g_vlo);

    int* workp;
    cudaGetSymbolAddress((void**)&workp, g_attn_work);

    const int WSZ = DMODEL * DMODEL;

    static int attr_set = 0;
    if (!attr_set) {
        cudaFuncSetAttribute(gemm_qkv, cudaFuncAttributeMaxDynamicSharedMemorySize,
                             2 * STAGE_B);
        cudaFuncSetAttribute(gemm_tc, cudaFuncAttributeMaxDynamicSharedMemorySize,
                             2 * STAGE_B);
        cudaFuncSetAttribute(attn_tc, cudaFuncAttributeMaxDynamicSharedMemorySize,
                             ATT_SMEM);
        attr_set = 1;
    }

    cudaMemsetAsync(workp, 0, sizeof(int));

    rope_table<<<(SEQ * 32 + 255) / 256, 256>>>();
    split_all<<<dim3((WQ4 + 255) / 256, 8), 256>>>(x, Wq, Wk, Wv, Wo,
                                                   xhi, xlo, whi, wlo);

    gemm_qkv<<<dim3(DMODEL / 128, SEQ / 128, 3), 128, 2 * STAGE_B>>>(
        xhi, xlo, whi, wlo, qhi, qlo, khi, klo, vhi, vlo);

    attn_tc<<<ATT_CTAS, 128, ATT_SMEM>>>(qhi, qlo, khi, klo, vhi, vlo, chi, clo);

    gemm_tc<<<dim3(DMODEL / 128, SEQ / 128), 128, 2 * STAGE_B>>>(
        chi, clo, whi + 3 * (size_t)WSZ, wlo + 3 * (size_t)WSZ, out);
}

// round 14
// speedup vs baseline: 1.1935x; 1.1935x over previous
#include <cuda_runtime.h>
#include <cuda_bf16.h>
#include <cuda_fp16.h>
#include <math.h>
#include <cstdint>

#define SEQ 4096
#define DMODEL 1024
#define NHEAD 16
#define DK 64

// ---------------------------------------------------------------------------
// Scratch (device globals — no runtime allocation allowed)
// ---------------------------------------------------------------------------
__device__ __align__(16) __nv_bfloat16 g_xhi[SEQ * DMODEL];
__device__ __align__(16) __nv_bfloat16 g_xlo[SEQ * DMODEL];
__device__ __align__(16) __nv_bfloat16 g_whi[4 * DMODEL * DMODEL];
__device__ __align__(16) __nv_bfloat16 g_wlo[4 * DMODEL * DMODEL];
__device__ __align__(16) __nv_bfloat16 g_chi[SEQ * DMODEL];
__device__ __align__(16) __nv_bfloat16 g_clo[SEQ * DMODEL];

__device__ __align__(16) __nv_bfloat16 g_qhi[SEQ * DMODEL];
__device__ __align__(16) __nv_bfloat16 g_qlo[SEQ * DMODEL];
__device__ __align__(16) __nv_bfloat16 g_khi[SEQ * DMODEL];
__device__ __align__(16) __nv_bfloat16 g_klo[SEQ * DMODEL];
__device__ __align__(16) __half        g_vf16[SEQ * DMODEL];

// rope cos/sin table: [pos][freq] -> (cos, sin), 4096 x 32 float2 = 1 MB
__device__ __align__(16) float2 g_ropetab[SEQ * 32];

// work-stealing counter for the persistent attention kernel (reset per launch)
__device__ int g_attn_work;

// ---------------------------------------------------------------------------
// Baseline-PTX helpers
// ---------------------------------------------------------------------------
__device__ __forceinline__ uint32_t smem_u32(const void* p) {
    uint32_t a;
    asm("{ .reg .u64 t; cvta.to.shared.u64 t, %1; cvt.u32.u64 %0, t; }"
        : "=r"(a) : "l"(p));
    return a;
}

__device__ __forceinline__ void cp16(uint32_t dst, const void* src) {
    asm volatile("cp.async.cg.shared.global [%0], [%1], 16;"
        :: "r"(dst), "l"(src) : "memory");
}
#define CP_COMMIT() asm volatile("cp.async.commit_group;" ::: "memory")
#define CP_WAIT1()  asm volatile("cp.async.wait_group 1;" ::: "memory")
#define CP_WAIT0()  asm volatile("cp.async.wait_group 0;" ::: "memory")

__device__ __forceinline__ void ldsm4(uint32_t r[4], uint32_t addr) {
    asm volatile("ldmatrix.sync.aligned.m8n8.x4.shared.b16 {%0,%1,%2,%3}, [%4];"
        : "=r"(r[0]), "=r"(r[1]), "=r"(r[2]), "=r"(r[3]) : "r"(addr));
}
__device__ __forceinline__ void ldsm4t(uint32_t r[4], uint32_t addr) {
    asm volatile("ldmatrix.sync.aligned.m8n8.x4.trans.shared.b16 {%0,%1,%2,%3}, [%4];"
        : "=r"(r[0]), "=r"(r[1]), "=r"(r[2]), "=r"(r[3]) : "r"(addr));
}

__device__ __forceinline__ void mma_bf16(float c[4], const uint32_t a[4],
                                         uint32_t b0, uint32_t b1) {
    asm volatile(
        "mma.sync.aligned.m16n8k16.row.col.f32.bf16.bf16.f32 "
        "{%0,%1,%2,%3}, {%4,%5,%6,%7}, {%8,%9}, {%0,%1,%2,%3};"
        : "+f"(c[0]), "+f"(c[1]), "+f"(c[2]), "+f"(c[3])
        : "r"(a[0]), "r"(a[1]), "r"(a[2]), "r"(a[3]), "r"(b0), "r"(b1));
}

__device__ __forceinline__ void mma_f16(float c[4], const uint32_t a[4],
                                        uint32_t b0, uint32_t b1) {
    asm volatile(
        "mma.sync.aligned.m16n8k16.row.col.f32.f16.f16.f32 "
        "{%0,%1,%2,%3}, {%4,%5,%6,%7}, {%8,%9}, {%0,%1,%2,%3};"
        : "+f"(c[0]), "+f"(c[1]), "+f"(c[2]), "+f"(c[3])
        : "r"(a[0]), "r"(a[1]), "r"(a[2]), "r"(a[3]), "r"(b0), "r"(b1));
}

__device__ __forceinline__ void split2(float a, float b, uint32_t& hi, uint32_t& lo) {
    __nv_bfloat16 ha = __float2bfloat16(a);
    __nv_bfloat16 hb = __float2bfloat16(b);
    __nv_bfloat162 hp(ha, hb);
    __nv_bfloat162 lp(__float2bfloat16(a - __bfloat162float(ha)),
                      __float2bfloat16(b - __bfloat162float(hb)));
    hi = *(uint32_t*)&hp;
    lo = *(uint32_t*)&lp;
}

__device__ __forceinline__ uint32_t packh2(float a, float b) {
    __half2 h = __floats2half2_rn(a, b);
    return *(uint32_t*)&h;
}

// ---------------------------------------------------------------------------
// rope table: angle(pos, i) = pos * 10000^(-i/32)
// ---------------------------------------------------------------------------
__global__ void rope_table()
{
    int idx = blockIdx.x * blockDim.x + threadIdx.x;
    if (idx >= SEQ * 32) return;
    const int pos = idx >> 5;
    const int i   = idx & 31;
    const float c1 = -9.210340371976184f / 32.0f;   // -ln(10000)/32
    const float ang = (float)pos * expf((float)i * c1);
    float sn, cs;
    sincosf(ang, &sn, &cs);
    g_ropetab[idx] = make_float2(cs, sn);
}

// ---------------------------------------------------------------------------
// Split x + the 4 weights into bf16 hi/lo.
// grid.y (8 slices of 256K float4): 0..3 -> quarters of x, 4..7 -> Wq..Wo
// ---------------------------------------------------------------------------
#define WQ4 (DMODEL * DMODEL / 4)   // 256K float4 per weight / per x-quarter

__global__ void split_all(const float* __restrict__ x,
                          const float* __restrict__ w0, const float* __restrict__ w1,
                          const float* __restrict__ w2, const float* __restrict__ w3,
                          __nv_bfloat16* __restrict__ xhi, __nv_bfloat16* __restrict__ xlo,
                          __nv_bfloat16* __restrict__ whi, __nv_bfloat16* __restrict__ wlo)
{
    const int sel = blockIdx.y;
    int i = blockIdx.x * blockDim.x + threadIdx.x;
    if (i >= WQ4) return;

    const float* src;
    __nv_bfloat16 *hi, *lo;
    size_t base;
    if (sel < 4) {
        src = x + (size_t)sel * WQ4 * 4;
        hi = xhi; lo = xlo;
        base = (size_t)sel * WQ4;
    } else {
        src = (sel == 4) ? w0 : (sel == 5) ? w1 : (sel == 6) ? w2 : w3;
        hi = whi; lo = wlo;
        base = (size_t)(sel - 4) * WQ4;
    }

    float4 v = ((const float4*)src)[i];
    uint32_t h0, l0, h1, l1;
    split2(v.x, v.y, h0, l0);
    split2(v.z, v.w, h1, l1);
    ((uint2*)hi)[base + i] = make_uint2(h0, h1);
    ((uint2*)lo)[base + i] = make_uint2(l0, l1);
}

// ---------------------------------------------------------------------------
// Tensor-core GEMM core (unchanged from 559us build)
// ---------------------------------------------------------------------------
#define BK 32
#define NT (DMODEL / BK)
#define TILE_B (128 * 64)
#define STAGE_B (4 * TILE_B)

struct GemmCore {
    float acc[4][8][4];
    int r0, c0;
};

__device__ __forceinline__ void gemm_mainloop(
    const __nv_bfloat16* __restrict__ Ahi, const __nv_bfloat16* __restrict__ Alo,
    const __nv_bfloat16* __restrict__ Bhi, const __nv_bfloat16* __restrict__ Blo,
    int bm, int bn, char* smem, GemmCore& core)
{
    const int tid  = threadIdx.x;
    const int wid  = tid >> 5, lane = tid & 31;
    const int wm   = wid & 1;
    const int wn   = wid >> 1;
    const uint32_t sbase = smem_u32(smem);

    const __nv_bfloat16* srcs[4] = {
        Ahi + (size_t)bm * DMODEL, Alo + (size_t)bm * DMODEL,
        Bhi + (size_t)bn * DMODEL, Blo + (size_t)bn * DMODEL };

    auto copy_stage = [&](int s, int k0) {
        const uint32_t stb = sbase + s * STAGE_B;
#pragma unroll
        for (int t = 0; t < 4; t++) {
            const __nv_bfloat16* base = srcs[t];
#pragma unroll
            for (int j = 0; j < 4; j++) {
                const int idx = j * 128 + tid;
                const int r = idx >> 2, c = idx & 3;
                const uint32_t pc = (uint32_t)(c ^ ((r >> 1) & 3));
                cp16(stb + t * TILE_B + (uint32_t)r * 64 + pc * 16,
                     base + (size_t)r * DMODEL + k0 + c * 8);
            }
        }
    };

    const int arow = wm * 64 + (lane & 15);
    const int ac0  = lane >> 4;
    const uint32_t aoff = (uint32_t)arow * 64 +
                          (uint32_t)((ac0 ^ ((arow >> 1) & 3)) * 16);
    const int brow = wn * 64 + ((lane >> 4) << 3) + (lane & 7);
    const int bc0  = (lane >> 3) & 1;
    const uint32_t boff = (uint32_t)brow * 64 +
                          (uint32_t)((bc0 ^ ((brow >> 1) & 3)) * 16);

#pragma unroll
    for (int i = 0; i < 4; i++)
#pragma unroll
        for (int j = 0; j < 8; j++)
#pragma unroll
            for (int q = 0; q < 4; q++) core.acc[i][j][q] = 0.f;

    copy_stage(0, 0);
    CP_COMMIT();

    for (int kt = 0; kt < NT; kt++) {
        const int s = kt & 1;
        if (kt + 1 < NT) {
            copy_stage(s ^ 1, (kt + 1) * BK);
            CP_COMMIT();
            CP_WAIT1();
        } else {
            CP_WAIT0();
        }
        __syncthreads();

        const uint32_t stb  = sbase + s * STAGE_B;
        const uint32_t sAhi = stb + aoff;
        const uint32_t sAlo = stb + TILE_B + aoff;
        const uint32_t sBhi = stb + 2 * TILE_B + boff;
        const uint32_t sBlo = stb + 3 * TILE_B + boff;

#pragma unroll
        for (int ks = 0; ks < 2; ks++) {
            const uint32_t kx = (uint32_t)(ks << 5);
            uint32_t ah[4][4], al[4][4], bh[4][4], bl[4][4];
#pragma unroll
            for (int mf = 0; mf < 4; mf++) {
                ldsm4(ah[mf], (sAhi + mf * 1024) ^ kx);
                ldsm4(al[mf], (sAlo + mf * 1024) ^ kx);
            }
#pragma unroll
            for (int np = 0; np < 4; np++) {
                ldsm4(bh[np], (sBhi + np * 1024) ^ kx);
                ldsm4(bl[np], (sBlo + np * 1024) ^ kx);
            }
#pragma unroll
            for (int mf = 0; mf < 4; mf++) {
#pragma unroll
                for (int nt = 0; nt < 8; nt++) {
                    const int np = nt >> 1, hh = (nt & 1) * 2;
                    mma_bf16(core.acc[mf][nt], ah[mf], bh[np][hh], bh[np][hh + 1]);
                    mma_bf16(core.acc[mf][nt], ah[mf], bl[np][hh], bl[np][hh + 1]);
                    mma_bf16(core.acc[mf][nt], al[mf], bh[np][hh], bh[np][hh + 1]);
                }
            }
        }
        __syncthreads();
    }

    core.r0 = bm + wm * 64 + (lane >> 2);
    core.c0 = bn + wn * 64 + (lane & 3) * 2;
}

// Fused QKV projection. z=0/1: rope (via table) + scale + split epilogue
// into q/k hi+lo. z=2: fp16 conversion into vf16.
__global__ __launch_bounds__(128, 2) void gemm_qkv(
    const __nv_bfloat16* __restrict__ Xhi, const __nv_bfloat16* __restrict__ Xlo,
    const __nv_bfloat16* __restrict__ Whi, const __nv_bfloat16* __restrict__ Wlo,
    __nv_bfloat16* __restrict__ Qhi, __nv_bfloat16* __restrict__ Qlo,
    __nv_bfloat16* __restrict__ Khi, __nv_bfloat16* __restrict__ Klo,
    __half* __restrict__ Vf)
{
    extern __shared__ __align__(1024) char smem[];
    const int z = blockIdx.z;
    const size_t woff = (size_t)z * DMODEL * DMODEL;

    GemmCore core;
    gemm_mainloop(Xhi, Xlo, Whi + woff, Wlo + woff,
                  blockIdx.y * 128, blockIdx.x * 128, smem, core);

    if (z == 2) {
#pragma unroll
        for (int mf = 0; mf < 4; mf++) {
#pragma unroll
            for (int nt = 0; nt < 8; nt++) {
                const size_t o0 = (size_t)(core.r0 + mf * 16) * DMODEL + core.c0 + nt * 8;
                const size_t o1 = (size_t)(core.r0 + mf * 16 + 8) * DMODEL + core.c0 + nt * 8;
                *(uint32_t*)&Vf[o0] = packh2(core.acc[mf][nt][0], core.acc[mf][nt][1]);
                *(uint32_t*)&Vf[o1] = packh2(core.acc[mf][nt][2], core.acc[mf][nt][3]);
            }
        }
    } else {
        __nv_bfloat16* Hi = (z == 0) ? Qhi : Khi;
        __nv_bfloat16* Lo = (z == 0) ? Qlo : Klo;
        const float scale = (z == 0) ? 0.125f : 1.0f;
#pragma unroll
        for (int nt = 0; nt < 8; nt++) {
            const int col  = core.c0 + nt * 8;
            const int freq = (col & 63) >> 1;
#pragma unroll
            for (int mf = 0; mf < 4; mf++) {
                const int row0 = core.r0 + mf * 16;
                float2 t0 = g_ropetab[row0 * 32 + freq];
                float x1 = core.acc[mf][nt][0], x2 = core.acc[mf][nt][1];
                uint32_t h, l;
                split2((x1 * t0.x - x2 * t0.y) * scale,
                       (x1 * t0.y + x2 * t0.x) * scale, h, l);
                const size_t o0 = (size_t)row0 * DMODEL + col;
                *(uint32_t*)&Hi[o0] = h; *(uint32_t*)&Lo[o0] = l;

                const int row1 = row0 + 8;
                float2 t1 = g_ropetab[row1 * 32 + freq];
                x1 = core.acc[mf][nt][2]; x2 = core.acc[mf][nt][3];
                split2((x1 * t1.x - x2 * t1.y) * scale,
                       (x1 * t1.y + x2 * t1.x) * scale, h, l);
                const size_t o1 = (size_t)row1 * DMODEL + col;
                *(uint32_t*)&Hi[o1] = h; *(uint32_t*)&Lo[o1] = l;
            }
        }
    }
}

__global__ __launch_bounds__(128, 2) void gemm_tc(
    const __nv_bfloat16* __restrict__ Ahi, const __nv_bfloat16* __restrict__ Alo,
    const __nv_bfloat16* __restrict__ Bhi, const __nv_bfloat16* __restrict__ Blo,
    float* __restrict__ C)
{
    extern __shared__ __align__(1024) char smem[];
    GemmCore core;
    gemm_mainloop(Ahi, Alo, Bhi, Blo, blockIdx.y * 128, blockIdx.x * 128, smem, core);
#pragma unroll
    for (int mf = 0; mf < 4; mf++) {
#pragma unroll
        for (int nt = 0; nt < 8; nt++) {
            float* p0 = &C[(size_t)(core.r0 + mf * 16) * DMODEL + core.c0 + nt * 8];
            float* p1 = &C[(size_t)(core.r0 + mf * 16 + 8) * DMODEL + core.c0 + nt * 8];
            *(float2*)p0 = make_float2(core.acc[mf][nt][0], core.acc[mf][nt][1]);
            *(float2*)p1 = make_float2(core.acc[mf][nt][2], core.acc[mf][nt][3]);
        }
    }
}

// ---------------------------------------------------------------------------
// PERSISTENT tensor-core causal flash attention.
// QK: bf16 hi/lo split (fp32-accurate scores).  PV: single-pass fp16
// (P and V fp16 — error ~3e-4, 8x better than bf16 single-pass).
// Stage = Khi | Klo | Vf16 (24 KB), double buffered; smem 80 KB.
// ---------------------------------------------------------------------------
#define ATT_TILE_B 8192
#define ATT_STAGE_B (3 * ATT_TILE_B)         // Khi, Klo, Vf16 = 24 KB
#define ATT_SMEM (32768 + 2 * ATT_STAGE_B)   // 80 KB
#define ATT_UNITS (32 * NHEAD)               // 512
#define ATT_CTAS 296                         // 2 per SM x 148 SMs

__global__ __launch_bounds__(128, 2) void attn_tc(
    const __nv_bfloat16* __restrict__ Qhi, const __nv_bfloat16* __restrict__ Qlo,
    const __nv_bfloat16* __restrict__ Khi, const __nv_bfloat16* __restrict__ Klo,
    const __half* __restrict__ Vf,
    __nv_bfloat16* __restrict__ Chi, __nv_bfloat16* __restrict__ Clo)
{
    extern __shared__ __align__(1024) char smem[];
    __shared__ int s_unit;
    const uint32_t sb = smem_u32(smem);
    const uint32_t qhib = sb, qlob = sb + 16384;
    const uint32_t stgb = sb + 32768;

    const int tid  = threadIdx.x;
    const int wid  = tid >> 5, lane = tid & 31;

    const uint32_t lx = (uint32_t)(lane & 7);
    uint32_t qoff[4], koff[4], voff[4];
#pragma unroll
    for (int ks = 0; ks < 4; ks++) {
        qoff[ks] = (uint32_t)(lane & 15) * 128 +
                   ((uint32_t)(ks * 2 + (lane >> 4)) ^ lx) * 16;
        koff[ks] = (uint32_t)(((lane >> 4) << 3) + (lane & 7)) * 128 +
                   ((uint32_t)(ks * 2 + ((lane >> 3) & 1)) ^ lx) * 16;
        voff[ks] = (uint32_t)(lane & 15) * 128 +
                   ((uint32_t)(ks * 2 + (lane >> 4)) ^ lx) * 16;
    }

    for (;;) {
        __syncthreads();
        if (tid == 0) s_unit = atomicAdd(&g_attn_work, 1);
        __syncthreads();
        const int u = s_unit;
        if (u >= ATT_UNITS) break;

        const int qtile = 31 - (u >> 4);     // LPT: largest tiles first
        const int h     = u & 15;
        const int hcol  = h * DK;
        const int q0 = qtile * 128;
        const int ntiles = qtile * 2 + 2;

#pragma unroll
        for (int j = 0; j < 8; j++) {
            const int idx = j * 128 + tid;
            const int r = idx >> 3, c = idx & 7;
            const uint32_t off = (uint32_t)r * 128 + ((uint32_t)c ^ (uint32_t)(r & 7)) * 16;
            const size_t g = (size_t)(q0 + r) * DMODEL + hcol + c * 8;
            cp16(qhib + off, Qhi + g);
            cp16(qlob + off, Qlo + g);
        }
        CP_COMMIT();

        {
            const uint32_t stb = stgb;
#pragma unroll
            for (int j = 0; j < 4; j++) {
                const int idx = j * 128 + tid;
                const int r = idx >> 3, c = idx & 7;
                const uint32_t off = (uint32_t)r * 128 + ((uint32_t)c ^ (uint32_t)(r & 7)) * 16;
                const size_t g = (size_t)r * DMODEL + hcol + c * 8;
                cp16(stb + off,                  Khi + g);
                cp16(stb + ATT_TILE_B + off,     Klo + g);
                cp16(stb + 2 * ATT_TILE_B + off, Vf + g);
            }
        }
        CP_COMMIT();

        CP_WAIT1();
        __syncthreads();

        uint32_t qh[2][4][4], ql[2][4][4];
        const uint32_t qrb = (uint32_t)(wid * 32) * 128;
#pragma unroll
        for (int mf = 0; mf < 2; mf++)
#pragma unroll
            for (int ks = 0; ks < 4; ks++) {
                ldsm4(qh[mf][ks], qhib + qrb + mf * 2048 + qoff[ks]);
                ldsm4(ql[mf][ks], qlob + qrb + mf * 2048 + qoff[ks]);
            }

        float O[2][8][4];
#pragma unroll
        for (int mf = 0; mf < 2; mf++)
#pragma unroll
            for (int f = 0; f < 8; f++)
#pragma unroll
                for (int q = 0; q < 4; q++) O[mf][f][q] = 0.f;
        float l0[2] = {0.f, 0.f}, l1[2] = {0.f, 0.f};

        int r0g[2], r1g[2];
#pragma unroll
        for (int mf = 0; mf < 2; mf++) {
            r0g[mf] = q0 + wid * 32 + mf * 16 + (lane >> 2);
            r1g[mf] = r0g[mf] + 8;
        }
        const int wrow_min = q0 + wid * 32;
        const int wrow_max = wrow_min + 31;

        for (int t = 0; t < ntiles; t++) {
            const int s = t & 1;
            if (t + 1 < ntiles) {
                const uint32_t stb = stgb + (s ^ 1) * ATT_STAGE_B;
                const int kn0 = (t + 1) * 64;
#pragma unroll
                for (int j = 0; j < 4; j++) {
                    const int idx = j * 128 + tid;
                    const int r = idx >> 3, c = idx & 7;
                    const uint32_t off = (uint32_t)r * 128 + ((uint32_t)c ^ (uint32_t)(r & 7)) * 16;
                    const size_t g = (size_t)(kn0 + r) * DMODEL + hcol + c * 8;
                    cp16(stb + off,                  Khi + g);
                    cp16(stb + ATT_TILE_B + off,     Klo + g);
                    cp16(stb + 2 * ATT_TILE_B + off, Vf + g);
                }
                CP_COMMIT();
                CP_WAIT1();
            } else {
                CP_WAIT0();
            }
            __syncthreads();

            const int k0 = t * 64;
            if (wrow_max >= k0) {
                const bool nomask = (k0 + 63) <= wrow_min;
                const uint32_t stb = stgb + s * ATT_STAGE_B;

#pragma unroll
                for (int np = 0; np < 4; np++) {
                    if (k0 + np * 16 > wrow_max) continue;   // P would be exactly 0

                    float s8[2][8];
#pragma unroll
                    for (int mf = 0; mf < 2; mf++)
#pragma unroll
                        for (int e = 0; e < 8; e++) s8[mf][e] = 0.f;
#pragma unroll
                    for (int ks = 0; ks < 4; ks++) {
                        uint32_t kh[4], kl[4];
                        const uint32_t ka = stb + (uint32_t)np * 2048 + koff[ks];
                        ldsm4(kh, ka);
                        ldsm4(kl, ka + ATT_TILE_B);
#pragma unroll
                        for (int mf = 0; mf < 2; mf++) {
                            mma_bf16(&s8[mf][0], qh[mf][ks], kh[0], kh[1]);
                            mma_bf16(&s8[mf][0], qh[mf][ks], kl[0], kl[1]);
                            mma_bf16(&s8[mf][0], ql[mf][ks], kh[0], kh[1]);
                            mma_bf16(&s8[mf][4], qh[mf][ks], kh[2], kh[3]);
                            mma_bf16(&s8[mf][4], qh[mf][ks], kl[2], kl[3]);
                            mma_bf16(&s8[mf][4], ql[mf][ks], kh[2], kh[3]);
                        }
                    }

                    const int c0 = k0 + np * 16 + ((lane & 3) << 1);
                    uint32_t Pf[2][4];
#pragma unroll
                    for (int mf = 0; mf < 2; mf++) {
                        float p[8];
                        if (nomask) {
#pragma unroll
                            for (int e = 0; e < 8; e++) p[e] = __expf(s8[mf][e]);
                        } else {
                            p[0] = (c0     <= r0g[mf]) ? __expf(s8[mf][0]) : 0.f;
                            p[1] = (c0 + 1 <= r0g[mf]) ? __expf(s8[mf][1]) : 0.f;
                            p[2] = (c0     <= r1g[mf]) ? __expf(s8[mf][2]) : 0.f;
                            p[3] = (c0 + 1 <= r1g[mf]) ? __expf(s8[mf][3]) : 0.f;
                            p[4] = (c0 + 8 <= r0g[mf]) ? __expf(s8[mf][4]) : 0.f;
                            p[5] = (c0 + 9 <= r0g[mf]) ? __expf(s8[mf][5]) : 0.f;
                            p[6] = (c0 + 8 <= r1g[mf]) ? __expf(s8[mf][6]) : 0.f;
                            p[7] = (c0 + 9 <= r1g[mf]) ? __expf(s8[mf][7]) : 0.f;
                        }
                        l0[mf] += (p[0] + p[1]) + (p[4] + p[5]);
                        l1[mf] += (p[2] + p[3]) + (p[6] + p[7]);
                        Pf[mf][0] = packh2(p[0], p[1]);
                        Pf[mf][1] = packh2(p[2], p[3]);
                        Pf[mf][2] = packh2(p[4], p[5]);
                        Pf[mf][3] = packh2(p[6], p[7]);
                    }

                    // PV: single-pass fp16
#pragma unroll
                    for (int dn = 0; dn < 4; dn++) {
                        uint32_t v4[4];
                        ldsm4t(v4, stb + 2 * ATT_TILE_B + (uint32_t)np * 2048 + voff[dn]);
#pragma unroll
                        for (int mf = 0; mf < 2; mf++) {
                            mma_f16(O[mf][dn * 2],     Pf[mf], v4[0], v4[1]);
                            mma_f16(O[mf][dn * 2 + 1], Pf[mf], v4[2], v4[3]);
                        }
                    }
                }
            }
            __syncthreads();
        }

        const int cbase = hcol + ((lane & 3) << 1);
#pragma unroll
        for (int mf = 0; mf < 2; mf++) {
            float a0 = l0[mf], a1 = l1[mf];
            a0 += __shfl_xor_sync(0xFFFFFFFF, a0, 1);
            a0 += __shfl_xor_sync(0xFFFFFFFF, a0, 2);
            a1 += __shfl_xor_sync(0xFFFFFFFF, a1, 1);
            a1 += __shfl_xor_sync(0xFFFFFFFF, a1, 2);
            const float inv0 = 1.f / a0, inv1 = 1.f / a1;
#pragma unroll
            for (int f = 0; f < 8; f++) {
                const size_t o0 = (size_t)r0g[mf] * DMODEL + cbase + f * 8;
                const size_t o1 = (size_t)r1g[mf] * DMODEL + cbase + f * 8;
                uint32_t hh, ll;
                split2(O[mf][f][0] * inv0, O[mf][f][1] * inv0, hh, ll);
                *(uint32_t*)&Chi[o0] = hh; *(uint32_t*)&Clo[o0] = ll;
                split2(O[mf][f][2] * inv1, O[mf][f][3] * inv1, hh, ll);
                *(uint32_t*)&Chi[o1] = hh; *(uint32_t*)&Clo[o1] = ll;
            }
        }
    }
}

// ---------------------------------------------------------------------------
extern "C" void kernel_launch(void* const* d_in, const int* in_sizes, int n_in,
                              void* d_out, int out_size)
{
    const float* x  = (const float*)d_in[0];
    const float* Wq = (const float*)d_in[1];
    const float* Wk = (const float*)d_in[2];
    const float* Wv = (const float*)d_in[3];
    const float* Wo = (const float*)d_in[4];
    float* out = (float*)d_out;

    __nv_bfloat16 *xhi, *xlo, *whi, *wlo, *chi, *clo;
    cudaGetSymbolAddress((void**)&xhi, g_xhi);
    cudaGetSymbolAddress((void**)&xlo, g_xlo);
    cudaGetSymbolAddress((void**)&whi, g_whi);
    cudaGetSymbolAddress((void**)&wlo, g_wlo);
    cudaGetSymbolAddress((void**)&chi, g_chi);
    cudaGetSymbolAddress((void**)&clo, g_clo);

    __nv_bfloat16 *qhi, *qlo, *khi, *klo;
    __half *vf;
    cudaGetSymbolAddress((void**)&qhi, g_qhi);
    cudaGetSymbolAddress((void**)&qlo, g_qlo);
    cudaGetSymbolAddress((void**)&khi, g_khi);
    cudaGetSymbolAddress((void**)&klo, g_klo);
    cudaGetSymbolAddress((void**)&vf,  g_vf16);

    int* workp;
    cudaGetSymbolAddress((void**)&workp, g_attn_work);

    const int WSZ = DMODEL * DMODEL;

    static int attr_set = 0;
    if (!attr_set) {
        cudaFuncSetAttribute(gemm_qkv, cudaFuncAttributeMaxDynamicSharedMemorySize,
                             2 * STAGE_B);
        cudaFuncSetAttribute(gemm_tc, cudaFuncAttributeMaxDynamicSharedMemorySize,
                             2 * STAGE_B);
        cudaFuncSetAttribute(attn_tc, cudaFuncAttributeMaxDynamicSharedMemorySize,
                             ATT_SMEM);
        attr_set = 1;
    }

    cudaMemsetAsync(workp, 0, sizeof(int));

    rope_table<<<(SEQ * 32 + 255) / 256, 256>>>();
    split_all<<<dim3((WQ4 + 255) / 256, 8), 256>>>(x, Wq, Wk, Wv, Wo,
                                                   xhi, xlo, whi, wlo);

    gemm_qkv<<<dim3(DMODEL / 128, SEQ / 128, 3), 128, 2 * STAGE_B>>>(
        xhi, xlo, whi, wlo, qhi, qlo, khi, klo, vf);

    attn_tc<<<ATT_CTAS, 128, ATT_SMEM>>>(qhi, qlo, khi, klo, vf, chi, clo);

    gemm_tc<<<dim3(DMODEL / 128, SEQ / 128), 128, 2 * STAGE_B>>>(
        chi, clo, whi + 3 * (size_t)WSZ, wlo + 3 * (size_t)WSZ, out);
}

// round 15
// speedup vs baseline: 1.3431x; 1.1254x over previous
#include <cuda_runtime.h>
#include <cuda_bf16.h>
#include <cuda_fp16.h>
#include <math.h>
#include <cstdint>

#define SEQ 4096
#define DMODEL 1024
#define NHEAD 16
#define DK 64

// ---------------------------------------------------------------------------
// Scratch (device globals — no runtime allocation allowed)
// ---------------------------------------------------------------------------
__device__ __align__(16) __nv_bfloat16 g_xhi[SEQ * DMODEL];
__device__ __align__(16) __nv_bfloat16 g_xlo[SEQ * DMODEL];
__device__ __align__(16) __nv_bfloat16 g_whi[4 * DMODEL * DMODEL];
__device__ __align__(16) __nv_bfloat16 g_wlo[4 * DMODEL * DMODEL];
__device__ __align__(16) __nv_bfloat16 g_chi[SEQ * DMODEL];
__device__ __align__(16) __nv_bfloat16 g_clo[SEQ * DMODEL];

__device__ __align__(16) __half g_qf16[SEQ * DMODEL];
__device__ __align__(16) __half g_kf16[SEQ * DMODEL];
__device__ __align__(16) __half g_vf16[SEQ * DMODEL];

// rope cos/sin table: [pos][freq] -> (cos, sin), 4096 x 32 float2 = 1 MB
__device__ __align__(16) float2 g_ropetab[SEQ * 32];

// work-stealing counter for the persistent attention kernel (reset per launch)
__device__ int g_attn_work;

// ---------------------------------------------------------------------------
// Baseline-PTX helpers
// ---------------------------------------------------------------------------
__device__ __forceinline__ uint32_t smem_u32(const void* p) {
    uint32_t a;
    asm("{ .reg .u64 t; cvta.to.shared.u64 t, %1; cvt.u32.u64 %0, t; }"
        : "=r"(a) : "l"(p));
    return a;
}

__device__ __forceinline__ void cp16(uint32_t dst, const void* src) {
    asm volatile("cp.async.cg.shared.global [%0], [%1], 16;"
        :: "r"(dst), "l"(src) : "memory");
}
#define CP_COMMIT() asm volatile("cp.async.commit_group;" ::: "memory")
#define CP_WAIT1()  asm volatile("cp.async.wait_group 1;" ::: "memory")
#define CP_WAIT0()  asm volatile("cp.async.wait_group 0;" ::: "memory")

__device__ __forceinline__ void ldsm4(uint32_t r[4], uint32_t addr) {
    asm volatile("ldmatrix.sync.aligned.m8n8.x4.shared.b16 {%0,%1,%2,%3}, [%4];"
        : "=r"(r[0]), "=r"(r[1]), "=r"(r[2]), "=r"(r[3]) : "r"(addr));
}
__device__ __forceinline__ void ldsm4t(uint32_t r[4], uint32_t addr) {
    asm volatile("ldmatrix.sync.aligned.m8n8.x4.trans.shared.b16 {%0,%1,%2,%3}, [%4];"
        : "=r"(r[0]), "=r"(r[1]), "=r"(r[2]), "=r"(r[3]) : "r"(addr));
}

__device__ __forceinline__ void mma_bf16(float c[4], const uint32_t a[4],
                                         uint32_t b0, uint32_t b1) {
    asm volatile(
        "mma.sync.aligned.m16n8k16.row.col.f32.bf16.bf16.f32 "
        "{%0,%1,%2,%3}, {%4,%5,%6,%7}, {%8,%9}, {%0,%1,%2,%3};"
        : "+f"(c[0]), "+f"(c[1]), "+f"(c[2]), "+f"(c[3])
        : "r"(a[0]), "r"(a[1]), "r"(a[2]), "r"(a[3]), "r"(b0), "r"(b1));
}

__device__ __forceinline__ void mma_f16(float c[4], const uint32_t a[4],
                                        uint32_t b0, uint32_t b1) {
    asm volatile(
        "mma.sync.aligned.m16n8k16.row.col.f32.f16.f16.f32 "
        "{%0,%1,%2,%3}, {%4,%5,%6,%7}, {%8,%9}, {%0,%1,%2,%3};"
        : "+f"(c[0]), "+f"(c[1]), "+f"(c[2]), "+f"(c[3])
        : "r"(a[0]), "r"(a[1]), "r"(a[2]), "r"(a[3]), "r"(b0), "r"(b1));
}

__device__ __forceinline__ void split2(float a, float b, uint32_t& hi, uint32_t& lo) {
    __nv_bfloat16 ha = __float2bfloat16(a);
    __nv_bfloat16 hb = __float2bfloat16(b);
    __nv_bfloat162 hp(ha, hb);
    __nv_bfloat162 lp(__float2bfloat16(a - __bfloat162float(ha)),
                      __float2bfloat16(b - __bfloat162float(hb)));
    hi = *(uint32_t*)&hp;
    lo = *(uint32_t*)&lp;
}

__device__ __forceinline__ uint32_t packh2(float a, float b) {
    __half2 h = __floats2half2_rn(a, b);
    return *(uint32_t*)&h;
}

// ---------------------------------------------------------------------------
// rope table: angle(pos, i) = pos * 10000^(-i/32)
// ---------------------------------------------------------------------------
__global__ void rope_table()
{
    int idx = blockIdx.x * blockDim.x + threadIdx.x;
    if (idx >= SEQ * 32) return;
    const int pos = idx >> 5;
    const int i   = idx & 31;
    const float c1 = -9.210340371976184f / 32.0f;   // -ln(10000)/32
    const float ang = (float)pos * expf((float)i * c1);
    float sn, cs;
    sincosf(ang, &sn, &cs);
    g_ropetab[idx] = make_float2(cs, sn);
}

// ---------------------------------------------------------------------------
// Split x + the 4 weights into bf16 hi/lo.
// grid.y (8 slices of 256K float4): 0..3 -> quarters of x, 4..7 -> Wq..Wo
// ---------------------------------------------------------------------------
#define WQ4 (DMODEL * DMODEL / 4)

__global__ void split_all(const float* __restrict__ x,
                          const float* __restrict__ w0, const float* __restrict__ w1,
                          const float* __restrict__ w2, const float* __restrict__ w3,
                          __nv_bfloat16* __restrict__ xhi, __nv_bfloat16* __restrict__ xlo,
                          __nv_bfloat16* __restrict__ whi, __nv_bfloat16* __restrict__ wlo)
{
    const int sel = blockIdx.y;
    int i = blockIdx.x * blockDim.x + threadIdx.x;
    if (i >= WQ4) return;

    const float* src;
    __nv_bfloat16 *hi, *lo;
    size_t base;
    if (sel < 4) {
        src = x + (size_t)sel * WQ4 * 4;
        hi = xhi; lo = xlo;
        base = (size_t)sel * WQ4;
    } else {
        src = (sel == 4) ? w0 : (sel == 5) ? w1 : (sel == 6) ? w2 : w3;
        hi = whi; lo = wlo;
        base = (size_t)(sel - 4) * WQ4;
    }

    float4 v = ((const float4*)src)[i];
    uint32_t h0, l0, h1, l1;
    split2(v.x, v.y, h0, l0);
    split2(v.z, v.w, h1, l1);
    ((uint2*)hi)[base + i] = make_uint2(h0, h1);
    ((uint2*)lo)[base + i] = make_uint2(l0, l1);
}

// ---------------------------------------------------------------------------
// Tensor-core GEMM core (unchanged — validated 3-pass bf16 hi/lo)
// ---------------------------------------------------------------------------
#define BK 32
#define NT (DMODEL / BK)
#define TILE_B (128 * 64)
#define STAGE_B (4 * TILE_B)

struct GemmCore {
    float acc[4][8][4];
    int r0, c0;
};

__device__ __forceinline__ void gemm_mainloop(
    const __nv_bfloat16* __restrict__ Ahi, const __nv_bfloat16* __restrict__ Alo,
    const __nv_bfloat16* __restrict__ Bhi, const __nv_bfloat16* __restrict__ Blo,
    int bm, int bn, char* smem, GemmCore& core)
{
    const int tid  = threadIdx.x;
    const int wid  = tid >> 5, lane = tid & 31;
    const int wm   = wid & 1;
    const int wn   = wid >> 1;
    const uint32_t sbase = smem_u32(smem);

    const __nv_bfloat16* srcs[4] = {
        Ahi + (size_t)bm * DMODEL, Alo + (size_t)bm * DMODEL,
        Bhi + (size_t)bn * DMODEL, Blo + (size_t)bn * DMODEL };

    auto copy_stage = [&](int s, int k0) {
        const uint32_t stb = sbase + s * STAGE_B;
#pragma unroll
        for (int t = 0; t < 4; t++) {
            const __nv_bfloat16* base = srcs[t];
#pragma unroll
            for (int j = 0; j < 4; j++) {
                const int idx = j * 128 + tid;
                const int r = idx >> 2, c = idx & 3;
                const uint32_t pc = (uint32_t)(c ^ ((r >> 1) & 3));
                cp16(stb + t * TILE_B + (uint32_t)r * 64 + pc * 16,
                     base + (size_t)r * DMODEL + k0 + c * 8);
            }
        }
    };

    const int arow = wm * 64 + (lane & 15);
    const int ac0  = lane >> 4;
    const uint32_t aoff = (uint32_t)arow * 64 +
                          (uint32_t)((ac0 ^ ((arow >> 1) & 3)) * 16);
    const int brow = wn * 64 + ((lane >> 4) << 3) + (lane & 7);
    const int bc0  = (lane >> 3) & 1;
    const uint32_t boff = (uint32_t)brow * 64 +
                          (uint32_t)((bc0 ^ ((brow >> 1) & 3)) * 16);

#pragma unroll
    for (int i = 0; i < 4; i++)
#pragma unroll
        for (int j = 0; j < 8; j++)
#pragma unroll
            for (int q = 0; q < 4; q++) core.acc[i][j][q] = 0.f;

    copy_stage(0, 0);
    CP_COMMIT();

    for (int kt = 0; kt < NT; kt++) {
        const int s = kt & 1;
        if (kt + 1 < NT) {
            copy_stage(s ^ 1, (kt + 1) * BK);
            CP_COMMIT();
            CP_WAIT1();
        } else {
            CP_WAIT0();
        }
        __syncthreads();

        const uint32_t stb  = sbase + s * STAGE_B;
        const uint32_t sAhi = stb + aoff;
        const uint32_t sAlo = stb + TILE_B + aoff;
        const uint32_t sBhi = stb + 2 * TILE_B + boff;
        const uint32_t sBlo = stb + 3 * TILE_B + boff;

#pragma unroll
        for (int ks = 0; ks < 2; ks++) {
            const uint32_t kx = (uint32_t)(ks << 5);
            uint32_t ah[4][4], al[4][4], bh[4][4], bl[4][4];
#pragma unroll
            for (int mf = 0; mf < 4; mf++) {
                ldsm4(ah[mf], (sAhi + mf * 1024) ^ kx);
                ldsm4(al[mf], (sAlo + mf * 1024) ^ kx);
            }
#pragma unroll
            for (int np = 0; np < 4; np++) {
                ldsm4(bh[np], (sBhi + np * 1024) ^ kx);
                ldsm4(bl[np], (sBlo + np * 1024) ^ kx);
            }
#pragma unroll
            for (int mf = 0; mf < 4; mf++) {
#pragma unroll
                for (int nt = 0; nt < 8; nt++) {
                    const int np = nt >> 1, hh = (nt & 1) * 2;
                    mma_bf16(core.acc[mf][nt], ah[mf], bh[np][hh], bh[np][hh + 1]);
                    mma_bf16(core.acc[mf][nt], ah[mf], bl[np][hh], bl[np][hh + 1]);
                    mma_bf16(core.acc[mf][nt], al[mf], bh[np][hh], bh[np][hh + 1]);
                }
            }
        }
        __syncthreads();
    }

    core.r0 = bm + wm * 64 + (lane >> 2);
    core.c0 = bn + wn * 64 + (lane & 3) * 2;
}

// Fused QKV projection. z=0/1: rope (via table) + scale, packed to fp16.
// z=2: fp16 conversion into vf16.
__global__ __launch_bounds__(128, 2) void gemm_qkv(
    const __nv_bfloat16* __restrict__ Xhi, const __nv_bfloat16* __restrict__ Xlo,
    const __nv_bfloat16* __restrict__ Whi, const __nv_bfloat16* __restrict__ Wlo,
    __half* __restrict__ Qf, __half* __restrict__ Kf, __half* __restrict__ Vf)
{
    extern __shared__ __align__(1024) char smem[];
    const int z = blockIdx.z;
    const size_t woff = (size_t)z * DMODEL * DMODEL;

    GemmCore core;
    gemm_mainloop(Xhi, Xlo, Whi + woff, Wlo + woff,
                  blockIdx.y * 128, blockIdx.x * 128, smem, core);

    if (z == 2) {
#pragma unroll
        for (int mf = 0; mf < 4; mf++) {
#pragma unroll
            for (int nt = 0; nt < 8; nt++) {
                const size_t o0 = (size_t)(core.r0 + mf * 16) * DMODEL + core.c0 + nt * 8;
                const size_t o1 = (size_t)(core.r0 + mf * 16 + 8) * DMODEL + core.c0 + nt * 8;
                *(uint32_t*)&Vf[o0] = packh2(core.acc[mf][nt][0], core.acc[mf][nt][1]);
                *(uint32_t*)&Vf[o1] = packh2(core.acc[mf][nt][2], core.acc[mf][nt][3]);
            }
        }
    } else {
        __half* Dst = (z == 0) ? Qf : Kf;
        const float scale = (z == 0) ? 0.125f : 1.0f;
#pragma unroll
        for (int nt = 0; nt < 8; nt++) {
            const int col  = core.c0 + nt * 8;
            const int freq = (col & 63) >> 1;
#pragma unroll
            for (int mf = 0; mf < 4; mf++) {
                const int row0 = core.r0 + mf * 16;
                float2 t0 = g_ropetab[row0 * 32 + freq];
                float x1 = core.acc[mf][nt][0], x2 = core.acc[mf][nt][1];
                const size_t o0 = (size_t)row0 * DMODEL + col;
                *(uint32_t*)&Dst[o0] = packh2((x1 * t0.x - x2 * t0.y) * scale,
                                              (x1 * t0.y + x2 * t0.x) * scale);

                const int row1 = row0 + 8;
                float2 t1 = g_ropetab[row1 * 32 + freq];
                x1 = core.acc[mf][nt][2]; x2 = core.acc[mf][nt][3];
                const size_t o1 = (size_t)row1 * DMODEL + col;
                *(uint32_t*)&Dst[o1] = packh2((x1 * t1.x - x2 * t1.y) * scale,
                                              (x1 * t1.y + x2 * t1.x) * scale);
            }
        }
    }
}

__global__ __launch_bounds__(128, 2) void gemm_tc(
    const __nv_bfloat16* __restrict__ Ahi, const __nv_bfloat16* __restrict__ Alo,
    const __nv_bfloat16* __restrict__ Bhi, const __nv_bfloat16* __restrict__ Blo,
    float* __restrict__ C)
{
    extern __shared__ __align__(1024) char smem[];
    GemmCore core;
    gemm_mainloop(Ahi, Alo, Bhi, Blo, blockIdx.y * 128, blockIdx.x * 128, smem, core);
#pragma unroll
    for (int mf = 0; mf < 4; mf++) {
#pragma unroll
        for (int nt = 0; nt < 8; nt++) {
            float* p0 = &C[(size_t)(core.r0 + mf * 16) * DMODEL + core.c0 + nt * 8];
            float* p1 = &C[(size_t)(core.r0 + mf * 16 + 8) * DMODEL + core.c0 + nt * 8];
            *(float2*)p0 = make_float2(core.acc[mf][nt][0], core.acc[mf][nt][1]);
            *(float2*)p1 = make_float2(core.acc[mf][nt][2], core.acc[mf][nt][3]);
        }
    }
}

// ---------------------------------------------------------------------------
// PERSISTENT tensor-core causal flash attention, ALL-fp16 single-pass
// (q, k, p, v fp16; fp32 accumulate; scores bounded so no max-subtraction).
// Q tile 16 KB + 2 stages x (K 8 KB + V 8 KB) = 48 KB -> 3 CTAs/SM.
// ---------------------------------------------------------------------------
#define ATT_TILE_B 8192
#define ATT_STAGE_B (2 * ATT_TILE_B)         // Kf, Vf = 16 KB
#define ATT_SMEM (16384 + 2 * ATT_STAGE_B)   // 48 KB
#define ATT_UNITS (32 * NHEAD)               // 512
#define ATT_CTAS 444                         // 3 per SM x 148 SMs

__global__ __launch_bounds__(128, 3) void attn_tc(
    const __half* __restrict__ Qf, const __half* __restrict__ Kf,
    const __half* __restrict__ Vf,
    __nv_bfloat16* __restrict__ Chi, __nv_bfloat16* __restrict__ Clo)
{
    extern __shared__ __align__(1024) char smem[];
    __shared__ int s_unit;
    const uint32_t sb = smem_u32(smem);
    const uint32_t qfb = sb;
    const uint32_t stgb = sb + 16384;

    const int tid  = threadIdx.x;
    const int wid  = tid >> 5, lane = tid & 31;

    const uint32_t lx = (uint32_t)(lane & 7);
    uint32_t qoff[4], koff[4], voff[4];
#pragma unroll
    for (int ks = 0; ks < 4; ks++) {
        qoff[ks] = (uint32_t)(lane & 15) * 128 +
                   ((uint32_t)(ks * 2 + (lane >> 4)) ^ lx) * 16;
        koff[ks] = (uint32_t)(((lane >> 4) << 3) + (lane & 7)) * 128 +
                   ((uint32_t)(ks * 2 + ((lane >> 3) & 1)) ^ lx) * 16;
        voff[ks] = (uint32_t)(lane & 15) * 128 +
                   ((uint32_t)(ks * 2 + (lane >> 4)) ^ lx) * 16;
    }

    for (;;) {
        __syncthreads();
        if (tid == 0) s_unit = atomicAdd(&g_attn_work, 1);
        __syncthreads();
        const int u = s_unit;
        if (u >= ATT_UNITS) break;

        const int qtile = 31 - (u >> 4);     // LPT: largest tiles first
        const int h     = u & 15;
        const int hcol  = h * DK;
        const int q0 = qtile * 128;
        const int ntiles = qtile * 2 + 2;

        // Q tile: 128 rows x 8 16B-chunks
#pragma unroll
        for (int j = 0; j < 8; j++) {
            const int idx = j * 128 + tid;
            const int r = idx >> 3, c = idx & 7;
            const uint32_t off = (uint32_t)r * 128 + ((uint32_t)c ^ (uint32_t)(r & 7)) * 16;
            cp16(qfb + off, Qf + (size_t)(q0 + r) * DMODEL + hcol + c * 8);
        }
        CP_COMMIT();

        // prefetch KV tile 0
        {
            const uint32_t stb = stgb;
#pragma unroll
            for (int j = 0; j < 4; j++) {
                const int idx = j * 128 + tid;
                const int r = idx >> 3, c = idx & 7;
                const uint32_t off = (uint32_t)r * 128 + ((uint32_t)c ^ (uint32_t)(r & 7)) * 16;
                const size_t g = (size_t)r * DMODEL + hcol + c * 8;
                cp16(stb + off,              Kf + g);
                cp16(stb + ATT_TILE_B + off, Vf + g);
            }
        }
        CP_COMMIT();

        CP_WAIT1();
        __syncthreads();

        uint32_t qf[2][4][4];
        const uint32_t qrb = (uint32_t)(wid * 32) * 128;
#pragma unroll
        for (int mf = 0; mf < 2; mf++)
#pragma unroll
            for (int ks = 0; ks < 4; ks++)
                ldsm4(qf[mf][ks], qfb + qrb + mf * 2048 + qoff[ks]);

        float O[2][8][4];
#pragma unroll
        for (int mf = 0; mf < 2; mf++)
#pragma unroll
            for (int f = 0; f < 8; f++)
#pragma unroll
                for (int q = 0; q < 4; q++) O[mf][f][q] = 0.f;
        float l0[2] = {0.f, 0.f}, l1[2] = {0.f, 0.f};

        int r0g[2], r1g[2];
#pragma unroll
        for (int mf = 0; mf < 2; mf++) {
            r0g[mf] = q0 + wid * 32 + mf * 16 + (lane >> 2);
            r1g[mf] = r0g[mf] + 8;
        }
        const int wrow_min = q0 + wid * 32;
        const int wrow_max = wrow_min + 31;

        for (int t = 0; t < ntiles; t++) {
            const int s = t & 1;
            if (t + 1 < ntiles) {
                const uint32_t stb = stgb + (s ^ 1) * ATT_STAGE_B;
                const int kn0 = (t + 1) * 64;
#pragma unroll
                for (int j = 0; j < 4; j++) {
                    const int idx = j * 128 + tid;
                    const int r = idx >> 3, c = idx & 7;
                    const uint32_t off = (uint32_t)r * 128 + ((uint32_t)c ^ (uint32_t)(r & 7)) * 16;
                    const size_t g = (size_t)(kn0 + r) * DMODEL + hcol + c * 8;
                    cp16(stb + off,              Kf + g);
                    cp16(stb + ATT_TILE_B + off, Vf + g);
                }
                CP_COMMIT();
                CP_WAIT1();
            } else {
                CP_WAIT0();
            }
            __syncthreads();

            const int k0 = t * 64;
            if (wrow_max >= k0) {
                const bool nomask = (k0 + 63) <= wrow_min;
                const uint32_t stb = stgb + s * ATT_STAGE_B;

#pragma unroll
                for (int np = 0; np < 4; np++) {
                    if (k0 + np * 16 > wrow_max) continue;   // P would be exactly 0

                    float s8[2][8];
#pragma unroll
                    for (int mf = 0; mf < 2; mf++)
#pragma unroll
                        for (int e = 0; e < 8; e++) s8[mf][e] = 0.f;
#pragma unroll
                    for (int ks = 0; ks < 4; ks++) {
                        uint32_t kv[4];
                        ldsm4(kv, stb + (uint32_t)np * 2048 + koff[ks]);
#pragma unroll
                        for (int mf = 0; mf < 2; mf++) {
                            mma_f16(&s8[mf][0], qf[mf][ks], kv[0], kv[1]);
                            mma_f16(&s8[mf][4], qf[mf][ks], kv[2], kv[3]);
                        }
                    }

                    const int c0 = k0 + np * 16 + ((lane & 3) << 1);
                    uint32_t Pf[2][4];
#pragma unroll
                    for (int mf = 0; mf < 2; mf++) {
                        float p[8];
                        if (nomask) {
#pragma unroll
                            for (int e = 0; e < 8; e++) p[e] = __expf(s8[mf][e]);
                        } else {
                            p[0] = (c0     <= r0g[mf]) ? __expf(s8[mf][0]) : 0.f;
                            p[1] = (c0 + 1 <= r0g[mf]) ? __expf(s8[mf][1]) : 0.f;
                            p[2] = (c0     <= r1g[mf]) ? __expf(s8[mf][2]) : 0.f;
                            p[3] = (c0 + 1 <= r1g[mf]) ? __expf(s8[mf][3]) : 0.f;
                            p[4] = (c0 + 8 <= r0g[mf]) ? __expf(s8[mf][4]) : 0.f;
                            p[5] = (c0 + 9 <= r0g[mf]) ? __expf(s8[mf][5]) : 0.f;
                            p[6] = (c0 + 8 <= r1g[mf]) ? __expf(s8[mf][6]) : 0.f;
                            p[7] = (c0 + 9 <= r1g[mf]) ? __expf(s8[mf][7]) : 0.f;
                        }
                        l0[mf] += (p[0] + p[1]) + (p[4] + p[5]);
                        l1[mf] += (p[2] + p[3]) + (p[6] + p[7]);
                        Pf[mf][0] = packh2(p[0], p[1]);
                        Pf[mf][1] = packh2(p[2], p[3]);
                        Pf[mf][2] = packh2(p[4], p[5]);
                        Pf[mf][3] = packh2(p[6], p[7]);
                    }

#pragma unroll
                    for (int dn = 0; dn < 4; dn++) {
                        uint32_t v4[4];
                        ldsm4t(v4, stb + ATT_TILE_B + (uint32_t)np * 2048 + voff[dn]);
#pragma unroll
                        for (int mf = 0; mf < 2; mf++) {
                            mma_f16(O[mf][dn * 2],     Pf[mf], v4[0], v4[1]);
                            mma_f16(O[mf][dn * 2 + 1], Pf[mf], v4[2], v4[3]);
                        }
                    }
                }
            }
            __syncthreads();
        }

        const int cbase = hcol + ((lane & 3) << 1);
#pragma unroll
        for (int mf = 0; mf < 2; mf++) {
            float a0 = l0[mf], a1 = l1[mf];
            a0 += __shfl_xor_sync(0xFFFFFFFF, a0, 1);
            a0 += __shfl_xor_sync(0xFFFFFFFF, a0, 2);
            a1 += __shfl_xor_sync(0xFFFFFFFF, a1, 1);
            a1 += __shfl_xor_sync(0xFFFFFFFF, a1, 2);
            const float inv0 = 1.f / a0, inv1 = 1.f / a1;
#pragma unroll
            for (int f = 0; f < 8; f++) {
                const size_t o0 = (size_t)r0g[mf] * DMODEL + cbase + f * 8;
                const size_t o1 = (size_t)r1g[mf] * DMODEL + cbase + f * 8;
                uint32_t hh, ll;
                split2(O[mf][f][0] * inv0, O[mf][f][1] * inv0, hh, ll);
                *(uint32_t*)&Chi[o0] = hh; *(uint32_t*)&Clo[o0] = ll;
                split2(O[mf][f][2] * inv1, O[mf][f][3] * inv1, hh, ll);
                *(uint32_t*)&Chi[o1] = hh; *(uint32_t*)&Clo[o1] = ll;
            }
        }
    }
}

// ---------------------------------------------------------------------------
extern "C" void kernel_launch(void* const* d_in, const int* in_sizes, int n_in,
                              void* d_out, int out_size)
{
    const float* x  = (const float*)d_in[0];
    const float* Wq = (const float*)d_in[1];
    const float* Wk = (const float*)d_in[2];
    const float* Wv = (const float*)d_in[3];
    const float* Wo = (const float*)d_in[4];
    float* out = (float*)d_out;

    __nv_bfloat16 *xhi, *xlo, *whi, *wlo, *chi, *clo;
    cudaGetSymbolAddress((void**)&xhi, g_xhi);
    cudaGetSymbolAddress((void**)&xlo, g_xlo);
    cudaGetSymbolAddress((void**)&whi, g_whi);
    cudaGetSymbolAddress((void**)&wlo, g_wlo);
    cudaGetSymbolAddress((void**)&chi, g_chi);
    cudaGetSymbolAddress((void**)&clo, g_clo);

    __half *qf, *kf, *vf;
    cudaGetSymbolAddress((void**)&qf, g_qf16);
    cudaGetSymbolAddress((void**)&kf, g_kf16);
    cudaGetSymbolAddress((void**)&vf, g_vf16);

    int* workp;
    cudaGetSymbolAddress((void**)&workp, g_attn_work);

    const int WSZ = DMODEL * DMODEL;

    static int attr_set = 0;
    if (!attr_set) {
        cudaFuncSetAttribute(gemm_qkv, cudaFuncAttributeMaxDynamicSharedMemorySize,
                             2 * STAGE_B);
        cudaFuncSetAttribute(gemm_tc, cudaFuncAttributeMaxDynamicSharedMemorySize,
                             2 * STAGE_B);
        cudaFuncSetAttribute(attn_tc, cudaFuncAttributeMaxDynamicSharedMemorySize,
                             ATT_SMEM);
        attr_set = 1;
    }

    cudaMemsetAsync(workp, 0, sizeof(int));

    rope_table<<<(SEQ * 32 + 255) / 256, 256>>>();
    split_all<<<dim3((WQ4 + 255) / 256, 8), 256>>>(x, Wq, Wk, Wv, Wo,
                                                   xhi, xlo, whi, wlo);

    gemm_qkv<<<dim3(DMODEL / 128, SEQ / 128, 3), 128, 2 * STAGE_B>>>(
        xhi, xlo, whi, wlo, qf, kf, vf);

    attn_tc<<<ATT_CTAS, 128, ATT_SMEM>>>(qf, kf, vf, chi, clo);

    gemm_tc<<<dim3(DMODEL / 128, SEQ / 128), 128, 2 * STAGE_B>>>(
        chi, clo, whi + 3 * (size_t)WSZ, wlo + 3 * (size_t)WSZ, out);
}

// round 16
// speedup vs baseline: 1.5774x; 1.1745x over previous
#include <cuda_runtime.h>
#include <cuda_bf16.h>
#include <cuda_fp16.h>
#include <math.h>
#include <cstdint>

#define SEQ 4096
#define DMODEL 1024
#define NHEAD 16
#define DK 64

// ---------------------------------------------------------------------------
// Scratch (device globals — no runtime allocation allowed)
// ---------------------------------------------------------------------------
__device__ __align__(16) __half g_xf16[SEQ * DMODEL];
__device__ __align__(16) __half g_wh[4 * DMODEL * DMODEL];
__device__ __align__(16) __half g_wl[4 * DMODEL * DMODEL];
__device__ __align__(16) __half g_cf16[SEQ * DMODEL];

__device__ __align__(16) __half g_qf16[SEQ * DMODEL];
__device__ __align__(16) __half g_kf16[SEQ * DMODEL];
__device__ __align__(16) __half g_vf16[SEQ * DMODEL];

// rope cos/sin table: [pos][freq] -> (cos, sin)
__device__ __align__(16) float2 g_ropetab[SEQ * 32];

// work-stealing counter (reset per launch)
__device__ int g_attn_work;

// ---------------------------------------------------------------------------
// Baseline-PTX helpers
// ---------------------------------------------------------------------------
__device__ __forceinline__ uint32_t smem_u32(const void* p) {
    uint32_t a;
    asm("{ .reg .u64 t; cvta.to.shared.u64 t, %1; cvt.u32.u64 %0, t; }"
        : "=r"(a) : "l"(p));
    return a;
}

__device__ __forceinline__ void cp16(uint32_t dst, const void* src) {
    asm volatile("cp.async.cg.shared.global [%0], [%1], 16;"
        :: "r"(dst), "l"(src) : "memory");
}
#define CP_COMMIT() asm volatile("cp.async.commit_group;" ::: "memory")
#define CP_WAIT1()  asm volatile("cp.async.wait_group 1;" ::: "memory")
#define CP_WAIT0()  asm volatile("cp.async.wait_group 0;" ::: "memory")

__device__ __forceinline__ void ldsm4(uint32_t r[4], uint32_t addr) {
    asm volatile("ldmatrix.sync.aligned.m8n8.x4.shared.b16 {%0,%1,%2,%3}, [%4];"
        : "=r"(r[0]), "=r"(r[1]), "=r"(r[2]), "=r"(r[3]) : "r"(addr));
}
__device__ __forceinline__ void ldsm4t(uint32_t r[4], uint32_t addr) {
    asm volatile("ldmatrix.sync.aligned.m8n8.x4.trans.shared.b16 {%0,%1,%2,%3}, [%4];"
        : "=r"(r[0]), "=r"(r[1]), "=r"(r[2]), "=r"(r[3]) : "r"(addr));
}

__device__ __forceinline__ void mma_f16(float c[4], const uint32_t a[4],
                                        uint32_t b0, uint32_t b1) {
    asm volatile(
        "mma.sync.aligned.m16n8k16.row.col.f32.f16.f16.f32 "
        "{%0,%1,%2,%3}, {%4,%5,%6,%7}, {%8,%9}, {%0,%1,%2,%3};"
        : "+f"(c[0]), "+f"(c[1]), "+f"(c[2]), "+f"(c[3])
        : "r"(a[0]), "r"(a[1]), "r"(a[2]), "r"(a[3]), "r"(b0), "r"(b1));
}

__device__ __forceinline__ uint32_t packh2(float a, float b) {
    __half2 h = __floats2half2_rn(a, b);
    return *(uint32_t*)&h;
}

// fp16 hi/lo split of a float pair: x = hi + lo + O(2^-21 |x|)
__device__ __forceinline__ void split2h(float a, float b, uint32_t& hi, uint32_t& lo) {
    __half ha = __float2half_rn(a);
    __half hb = __float2half_rn(b);
    __half2 hp(ha, hb);
    __half2 lp(__float2half_rn(a - __half2float(ha)),
               __float2half_rn(b - __half2float(hb)));
    hi = *(uint32_t*)&hp;
    lo = *(uint32_t*)&lp;
}

// ---------------------------------------------------------------------------
// rope table: angle(pos, i) = pos * 10000^(-i/32)
// ---------------------------------------------------------------------------
__global__ void rope_table()
{
    int idx = blockIdx.x * blockDim.x + threadIdx.x;
    if (idx >= SEQ * 32) return;
    const int pos = idx >> 5;
    const int i   = idx & 31;
    const float c1 = -9.210340371976184f / 32.0f;   // -ln(10000)/32
    const float ang = (float)pos * expf((float)i * c1);
    float sn, cs;
    sincosf(ang, &sn, &cs);
    g_ropetab[idx] = make_float2(cs, sn);
}

// ---------------------------------------------------------------------------
// Convert inputs: x -> fp16 single; Wq..Wo -> fp16 hi/lo.
// grid.y (8 slices of 256K float4): 0..3 -> x quarters, 4..7 -> weights
// ---------------------------------------------------------------------------
#define WQ4 (DMODEL * DMODEL / 4)

__global__ void split_all(const float* __restrict__ x,
                          const float* __restrict__ w0, const float* __restrict__ w1,
                          const float* __restrict__ w2, const float* __restrict__ w3,
                          __half* __restrict__ xf,
                          __half* __restrict__ wh, __half* __restrict__ wl)
{
    const int sel = blockIdx.y;
    int i = blockIdx.x * blockDim.x + threadIdx.x;
    if (i >= WQ4) return;

    if (sel < 4) {
        const float* src = x + (size_t)sel * WQ4 * 4;
        float4 v = ((const float4*)src)[i];
        ((uint2*)xf)[(size_t)sel * WQ4 + i] =
            make_uint2(packh2(v.x, v.y), packh2(v.z, v.w));
    } else {
        const float* src = (sel == 4) ? w0 : (sel == 5) ? w1 : (sel == 6) ? w2 : w3;
        const size_t base = (size_t)(sel - 4) * WQ4;
        float4 v = ((const float4*)src)[i];
        uint32_t h0, l0, h1, l1;
        split2h(v.x, v.y, h0, l0);
        split2h(v.z, v.w, h1, l1);
        ((uint2*)wh)[base + i] = make_uint2(h0, h1);
        ((uint2*)wl)[base + i] = make_uint2(l0, l1);
    }
}

// ---------------------------------------------------------------------------
// Tensor-core GEMM, 2-pass fp16: C = A * (Wh + Wl)^T, fp32 accumulate.
// 128x128 CTA tile, 4 warps (2x2), 64x64 warp tile, BK=32, double buffered.
// ---------------------------------------------------------------------------
#define BK 32
#define NT (DMODEL / BK)
#define TILE_B (128 * 64)           // 8 KB per operand tile
#define STAGE_B (3 * TILE_B)        // A, Wh, Wl = 24 KB

struct GemmCore {
    float acc[4][8][4];
    int r0, c0;
};

__device__ __forceinline__ void gemm_mainloop(
    const __half* __restrict__ A,
    const __half* __restrict__ Bh, const __half* __restrict__ Bl,
    int bm, int bn, char* smem, GemmCore& core)
{
    const int tid  = threadIdx.x;
    const int wid  = tid >> 5, lane = tid & 31;
    const int wm   = wid & 1;
    const int wn   = wid >> 1;
    const uint32_t sbase = smem_u32(smem);

    const __half* srcs[3] = {
        A + (size_t)bm * DMODEL,
        Bh + (size_t)bn * DMODEL,
        Bl + (size_t)bn * DMODEL };

    auto copy_stage = [&](int s, int k0) {
        const uint32_t stb = sbase + s * STAGE_B;
#pragma unroll
        for (int t = 0; t < 3; t++) {
            const __half* base = srcs[t];
#pragma unroll
            for (int j = 0; j < 4; j++) {
                const int idx = j * 128 + tid;
                const int r = idx >> 2, c = idx & 3;
                const uint32_t pc = (uint32_t)(c ^ ((r >> 1) & 3));
                cp16(stb + t * TILE_B + (uint32_t)r * 64 + pc * 16,
                     base + (size_t)r * DMODEL + k0 + c * 8);
            }
        }
    };

    const int arow = wm * 64 + (lane & 15);
    const int ac0  = lane >> 4;
    const uint32_t aoff = (uint32_t)arow * 64 +
                          (uint32_t)((ac0 ^ ((arow >> 1) & 3)) * 16);
    const int brow = wn * 64 + ((lane >> 4) << 3) + (lane & 7);
    const int bc0  = (lane >> 3) & 1;
    const uint32_t boff = (uint32_t)brow * 64 +
                          (uint32_t)((bc0 ^ ((brow >> 1) & 3)) * 16);

#pragma unroll
    for (int i = 0; i < 4; i++)
#pragma unroll
        for (int j = 0; j < 8; j++)
#pragma unroll
            for (int q = 0; q < 4; q++) core.acc[i][j][q] = 0.f;

    copy_stage(0, 0);
    CP_COMMIT();

    for (int kt = 0; kt < NT; kt++) {
        const int s = kt & 1;
        if (kt + 1 < NT) {
            copy_stage(s ^ 1, (kt + 1) * BK);
            CP_COMMIT();
            CP_WAIT1();
        } else {
            CP_WAIT0();
        }
        __syncthreads();

        const uint32_t stb = sbase + s * STAGE_B;
        const uint32_t sA  = stb + aoff;
        const uint32_t sBh = stb + TILE_B + boff;
        const uint32_t sBl = stb + 2 * TILE_B + boff;

#pragma unroll
        for (int ks = 0; ks < 2; ks++) {
            const uint32_t kx = (uint32_t)(ks << 5);
            uint32_t af[4][4], bh[4][4], bl[4][4];
#pragma unroll
            for (int mf = 0; mf < 4; mf++)
                ldsm4(af[mf], (sA + mf * 1024) ^ kx);
#pragma unroll
            for (int np = 0; np < 4; np++) {
                ldsm4(bh[np], (sBh + np * 1024) ^ kx);
                ldsm4(bl[np], (sBl + np * 1024) ^ kx);
            }
#pragma unroll
            for (int mf = 0; mf < 4; mf++) {
#pragma unroll
                for (int nt = 0; nt < 8; nt++) {
                    const int np = nt >> 1, hh = (nt & 1) * 2;
                    mma_f16(core.acc[mf][nt], af[mf], bh[np][hh], bh[np][hh + 1]);
                    mma_f16(core.acc[mf][nt], af[mf], bl[np][hh], bl[np][hh + 1]);
                }
            }
        }
        __syncthreads();
    }

    core.r0 = bm + wm * 64 + (lane >> 2);
    core.c0 = bn + wn * 64 + (lane & 3) * 2;
}

// Fused QKV projection. z=0/1: rope (table) + scale, packed fp16.
// z=2: fp16 pack into vf16.
__global__ __launch_bounds__(128, 2) void gemm_qkv(
    const __half* __restrict__ Xf,
    const __half* __restrict__ Wh, const __half* __restrict__ Wl,
    __half* __restrict__ Qf, __half* __restrict__ Kf, __half* __restrict__ Vf)
{
    extern __shared__ __align__(1024) char smem[];
    const int z = blockIdx.z;
    const size_t woff = (size_t)z * DMODEL * DMODEL;

    GemmCore core;
    gemm_mainloop(Xf, Wh + woff, Wl + woff,
                  blockIdx.y * 128, blockIdx.x * 128, smem, core);

    if (z == 2) {
#pragma unroll
        for (int mf = 0; mf < 4; mf++) {
#pragma unroll
            for (int nt = 0; nt < 8; nt++) {
                const size_t o0 = (size_t)(core.r0 + mf * 16) * DMODEL + core.c0 + nt * 8;
                const size_t o1 = (size_t)(core.r0 + mf * 16 + 8) * DMODEL + core.c0 + nt * 8;
                *(uint32_t*)&Vf[o0] = packh2(core.acc[mf][nt][0], core.acc[mf][nt][1]);
                *(uint32_t*)&Vf[o1] = packh2(core.acc[mf][nt][2], core.acc[mf][nt][3]);
            }
        }
    } else {
        __half* Dst = (z == 0) ? Qf : Kf;
        const float scale = (z == 0) ? 0.125f : 1.0f;
#pragma unroll
        for (int nt = 0; nt < 8; nt++) {
            const int col  = core.c0 + nt * 8;
            const int freq = (col & 63) >> 1;
#pragma unroll
            for (int mf = 0; mf < 4; mf++) {
                const int row0 = core.r0 + mf * 16;
                float2 t0 = g_ropetab[row0 * 32 + freq];
                float x1 = core.acc[mf][nt][0], x2 = core.acc[mf][nt][1];
                const size_t o0 = (size_t)row0 * DMODEL + col;
                *(uint32_t*)&Dst[o0] = packh2((x1 * t0.x - x2 * t0.y) * scale,
                                              (x1 * t0.y + x2 * t0.x) * scale);

                const int row1 = row0 + 8;
                float2 t1 = g_ropetab[row1 * 32 + freq];
                x1 = core.acc[mf][nt][2]; x2 = core.acc[mf][nt][3];
                const size_t o1 = (size_t)row1 * DMODEL + col;
                *(uint32_t*)&Dst[o1] = packh2((x1 * t1.x - x2 * t1.y) * scale,
                                              (x1 * t1.y + x2 * t1.x) * scale);
            }
        }
    }
}

// Output projection: A = ctx (fp16), B = Wo (fp16 hi/lo), fp32 out.
__global__ __launch_bounds__(128, 2) void gemm_tc(
    const __half* __restrict__ A,
    const __half* __restrict__ Bh, const __half* __restrict__ Bl,
    float* __restrict__ C)
{
    extern __shared__ __align__(1024) char smem[];
    GemmCore core;
    gemm_mainloop(A, Bh, Bl, blockIdx.y * 128, blockIdx.x * 128, smem, core);
#pragma unroll
    for (int mf = 0; mf < 4; mf++) {
#pragma unroll
        for (int nt = 0; nt < 8; nt++) {
            float* p0 = &C[(size_t)(core.r0 + mf * 16) * DMODEL + core.c0 + nt * 8];
            float* p1 = &C[(size_t)(core.r0 + mf * 16 + 8) * DMODEL + core.c0 + nt * 8];
            *(float2*)p0 = make_float2(core.acc[mf][nt][0], core.acc[mf][nt][1]);
            *(float2*)p1 = make_float2(core.acc[mf][nt][2], core.acc[mf][nt][3]);
        }
    }
}

// ---------------------------------------------------------------------------
// PERSISTENT tensor-core causal flash attention, all-fp16 single-pass.
// Epilogue writes ctx as single fp16 (feeds the fp16 output projection).
// ---------------------------------------------------------------------------
#define ATT_TILE_B 8192
#define ATT_STAGE_B (2 * ATT_TILE_B)         // Kf, Vf = 16 KB
#define ATT_SMEM (16384 + 2 * ATT_STAGE_B)   // 48 KB
#define ATT_UNITS (32 * NHEAD)               // 512
#define ATT_CTAS 444                         // 3 per SM x 148 SMs

__global__ __launch_bounds__(128, 3) void attn_tc(
    const __half* __restrict__ Qf, const __half* __restrict__ Kf,
    const __half* __restrict__ Vf, __half* __restrict__ Cf)
{
    extern __shared__ __align__(1024) char smem[];
    __shared__ int s_unit;
    const uint32_t sb = smem_u32(smem);
    const uint32_t qfb = sb;
    const uint32_t stgb = sb + 16384;

    const int tid  = threadIdx.x;
    const int wid  = tid >> 5, lane = tid & 31;

    const uint32_t lx = (uint32_t)(lane & 7);
    uint32_t qoff[4], koff[4], voff[4];
#pragma unroll
    for (int ks = 0; ks < 4; ks++) {
        qoff[ks] = (uint32_t)(lane & 15) * 128 +
                   ((uint32_t)(ks * 2 + (lane >> 4)) ^ lx) * 16;
        koff[ks] = (uint32_t)(((lane >> 4) << 3) + (lane & 7)) * 128 +
                   ((uint32_t)(ks * 2 + ((lane >> 3) & 1)) ^ lx) * 16;
        voff[ks] = (uint32_t)(lane & 15) * 128 +
                   ((uint32_t)(ks * 2 + (lane >> 4)) ^ lx) * 16;
    }

    for (;;) {
        __syncthreads();
        if (tid == 0) s_unit = atomicAdd(&g_attn_work, 1);
        __syncthreads();
        const int u = s_unit;
        if (u >= ATT_UNITS) break;

        const int qtile = 31 - (u >> 4);     // LPT: largest tiles first
        const int h     = u & 15;
        const int hcol  = h * DK;
        const int q0 = qtile * 128;
        const int ntiles = qtile * 2 + 2;

#pragma unroll
        for (int j = 0; j < 8; j++) {
            const int idx = j * 128 + tid;
            const int r = idx >> 3, c = idx & 7;
            const uint32_t off = (uint32_t)r * 128 + ((uint32_t)c ^ (uint32_t)(r & 7)) * 16;
            cp16(qfb + off, Qf + (size_t)(q0 + r) * DMODEL + hcol + c * 8);
        }
        CP_COMMIT();

        {
            const uint32_t stb = stgb;
#pragma unroll
            for (int j = 0; j < 4; j++) {
                const int idx = j * 128 + tid;
                const int r = idx >> 3, c = idx & 7;
                const uint32_t off = (uint32_t)r * 128 + ((uint32_t)c ^ (uint32_t)(r & 7)) * 16;
                const size_t g = (size_t)r * DMODEL + hcol + c * 8;
                cp16(stb + off,              Kf + g);
                cp16(stb + ATT_TILE_B + off, Vf + g);
            }
        }
        CP_COMMIT();

        CP_WAIT1();
        __syncthreads();

        uint32_t qf[2][4][4];
        const uint32_t qrb = (uint32_t)(wid * 32) * 128;
#pragma unroll
        for (int mf = 0; mf < 2; mf++)
#pragma unroll
            for (int ks = 0; ks < 4; ks++)
                ldsm4(qf[mf][ks], qfb + qrb + mf * 2048 + qoff[ks]);

        float O[2][8][4];
#pragma unroll
        for (int mf = 0; mf < 2; mf++)
#pragma unroll
            for (int f = 0; f < 8; f++)
#pragma unroll
                for (int q = 0; q < 4; q++) O[mf][f][q] = 0.f;
        float l0[2] = {0.f, 0.f}, l1[2] = {0.f, 0.f};

        int r0g[2], r1g[2];
#pragma unroll
        for (int mf = 0; mf < 2; mf++) {
            r0g[mf] = q0 + wid * 32 + mf * 16 + (lane >> 2);
            r1g[mf] = r0g[mf] + 8;
        }
        const int wrow_min = q0 + wid * 32;
        const int wrow_max = wrow_min + 31;

        for (int t = 0; t < ntiles; t++) {
            const int s = t & 1;
            if (t + 1 < ntiles) {
                const uint32_t stb = stgb + (s ^ 1) * ATT_STAGE_B;
                const int kn0 = (t + 1) * 64;
#pragma unroll
                for (int j = 0; j < 4; j++) {
                    const int idx = j * 128 + tid;
                    const int r = idx >> 3, c = idx & 7;
                    const uint32_t off = (uint32_t)r * 128 + ((uint32_t)c ^ (uint32_t)(r & 7)) * 16;
                    const size_t g = (size_t)(kn0 + r) * DMODEL + hcol + c * 8;
                    cp16(stb + off,              Kf + g);
                    cp16(stb + ATT_TILE_B + off, Vf + g);
                }
                CP_COMMIT();
                CP_WAIT1();
            } else {
                CP_WAIT0();
            }
            __syncthreads();

            const int k0 = t * 64;
            if (wrow_max >= k0) {
                const bool nomask = (k0 + 63) <= wrow_min;
                const uint32_t stb = stgb + s * ATT_STAGE_B;

#pragma unroll
                for (int np = 0; np < 4; np++) {
                    if (k0 + np * 16 > wrow_max) continue;   // P would be exactly 0

                    float s8[2][8];
#pragma unroll
                    for (int mf = 0; mf < 2; mf++)
#pragma unroll
                        for (int e = 0; e < 8; e++) s8[mf][e] = 0.f;
#pragma unroll
                    for (int ks = 0; ks < 4; ks++) {
                        uint32_t kv[4];
                        ldsm4(kv, stb + (uint32_t)np * 2048 + koff[ks]);
#pragma unroll
                        for (int mf = 0; mf < 2; mf++) {
                            mma_f16(&s8[mf][0], qf[mf][ks], kv[0], kv[1]);
                            mma_f16(&s8[mf][4], qf[mf][ks], kv[2], kv[3]);
                        }
                    }

                    const int c0 = k0 + np * 16 + ((lane & 3) << 1);
                    uint32_t Pf[2][4];
#pragma unroll
                    for (int mf = 0; mf < 2; mf++) {
                        float p[8];
                        if (nomask) {
#pragma unroll
                            for (int e = 0; e < 8; e++) p[e] = __expf(s8[mf][e]);
                        } else {
                            p[0] = (c0     <= r0g[mf]) ? __expf(s8[mf][0]) : 0.f;
                            p[1] = (c0 + 1 <= r0g[mf]) ? __expf(s8[mf][1]) : 0.f;
                            p[2] = (c0     <= r1g[mf]) ? __expf(s8[mf][2]) : 0.f;
                            p[3] = (c0 + 1 <= r1g[mf]) ? __expf(s8[mf][3]) : 0.f;
                            p[4] = (c0 + 8 <= r0g[mf]) ? __expf(s8[mf][4]) : 0.f;
                            p[5] = (c0 + 9 <= r0g[mf]) ? __expf(s8[mf][5]) : 0.f;
                            p[6] = (c0 + 8 <= r1g[mf]) ? __expf(s8[mf][6]) : 0.f;
                            p[7] = (c0 + 9 <= r1g[mf]) ? __expf(s8[mf][7]) : 0.f;
                        }
                        l0[mf] += (p[0] + p[1]) + (p[4] + p[5]);
                        l1[mf] += (p[2] + p[3]) + (p[6] + p[7]);
                        Pf[mf][0] = packh2(p[0], p[1]);
                        Pf[mf][1] = packh2(p[2], p[3]);
                        Pf[mf][2] = packh2(p[4], p[5]);
                        Pf[mf][3] = packh2(p[6], p[7]);
                    }

#pragma unroll
                    for (int dn = 0; dn < 4; dn++) {
                        uint32_t v4[4];
                        ldsm4t(v4, stb + ATT_TILE_B + (uint32_t)np * 2048 + voff[dn]);
#pragma unroll
                        for (int mf = 0; mf < 2; mf++) {
                            mma_f16(O[mf][dn * 2],     Pf[mf], v4[0], v4[1]);
                            mma_f16(O[mf][dn * 2 + 1], Pf[mf], v4[2], v4[3]);
                        }
                    }
                }
            }
            __syncthreads();
        }

        const int cbase = hcol + ((lane & 3) << 1);
#pragma unroll
        for (int mf = 0; mf < 2; mf++) {
            float a0 = l0[mf], a1 = l1[mf];
            a0 += __shfl_xor_sync(0xFFFFFFFF, a0, 1);
            a0 += __shfl_xor_sync(0xFFFFFFFF, a0, 2);
            a1 += __shfl_xor_sync(0xFFFFFFFF, a1, 1);
            a1 += __shfl_xor_sync(0xFFFFFFFF, a1, 2);
            const float inv0 = 1.f / a0, inv1 = 1.f / a1;
#pragma unroll
            for (int f = 0; f < 8; f++) {
                const size_t o0 = (size_t)r0g[mf] * DMODEL + cbase + f * 8;
                const size_t o1 = (size_t)r1g[mf] * DMODEL + cbase + f * 8;
                *(uint32_t*)&Cf[o0] = packh2(O[mf][f][0] * inv0, O[mf][f][1] * inv0);
                *(uint32_t*)&Cf[o1] = packh2(O[mf][f][2] * inv1, O[mf][f][3] * inv1);
            }
        }
    }
}

// ---------------------------------------------------------------------------
extern "C" void kernel_launch(void* const* d_in, const int* in_sizes, int n_in,
                              void* d_out, int out_size)
{
    const float* x  = (const float*)d_in[0];
    const float* Wq = (const float*)d_in[1];
    const float* Wk = (const float*)d_in[2];
    const float* Wv = (const float*)d_in[3];
    const float* Wo = (const float*)d_in[4];
    float* out = (float*)d_out;

    __half *xf, *wh, *wl, *cf, *qf, *kf, *vf;
    cudaGetSymbolAddress((void**)&xf, g_xf16);
    cudaGetSymbolAddress((void**)&wh, g_wh);
    cudaGetSymbolAddress((void**)&wl, g_wl);
    cudaGetSymbolAddress((void**)&cf, g_cf16);
    cudaGetSymbolAddress((void**)&qf, g_qf16);
    cudaGetSymbolAddress((void**)&kf, g_kf16);
    cudaGetSymbolAddress((void**)&vf, g_vf16);

    int* workp;
    cudaGetSymbolAddress((void**)&workp, g_attn_work);

    const int WSZ = DMODEL * DMODEL;

    static int attr_set = 0;
    if (!attr_set) {
        cudaFuncSetAttribute(gemm_qkv, cudaFuncAttributeMaxDynamicSharedMemorySize,
                             2 * STAGE_B);
        cudaFuncSetAttribute(gemm_tc, cudaFuncAttributeMaxDynamicSharedMemorySize,
                             2 * STAGE_B);
        cudaFuncSetAttribute(attn_tc, cudaFuncAttributeMaxDynamicSharedMemorySize,
                             ATT_SMEM);
        attr_set = 1;
    }

    cudaMemsetAsync(workp, 0, sizeof(int));

    rope_table<<<(SEQ * 32 + 255) / 256, 256>>>();
    split_all<<<dim3((WQ4 + 255) / 256, 8), 256>>>(x, Wq, Wk, Wv, Wo, xf, wh, wl);

    gemm_qkv<<<dim3(DMODEL / 128, SEQ / 128, 3), 128, 2 * STAGE_B>>>(
        xf, wh, wl, qf, kf, vf);

    attn_tc<<<ATT_CTAS, 128, ATT_SMEM>>>(qf, kf, vf, cf);

    gemm_tc<<<dim3(DMODEL / 128, SEQ / 128), 128, 2 * STAGE_B>>>(
        cf, wh + 3 * (size_t)WSZ, wl + 3 * (size_t)WSZ, out);
}

// round 17
// speedup vs baseline: 1.8778x; 1.1905x over previous
#include <cuda_runtime.h>
#include <cuda_bf16.h>
#include <cuda_fp16.h>
#include <math.h>
#include <cstdint>

#define SEQ 4096
#define DMODEL 1024
#define NHEAD 16
#define DK 64

// ---------------------------------------------------------------------------
// Scratch (device globals — no runtime allocation allowed)
// ---------------------------------------------------------------------------
__device__ __align__(16) __half g_xf16[SEQ * DMODEL];
__device__ __align__(16) __half g_wh[4 * DMODEL * DMODEL];
__device__ __align__(16) __half g_wl[DMODEL * DMODEL];      // lo only for Wo
__device__ __align__(16) __half g_cf16[SEQ * DMODEL];

__device__ __align__(16) __half g_qf16[SEQ * DMODEL];
__device__ __align__(16) __half g_kf16[SEQ * DMODEL];
__device__ __align__(16) __half g_vf16[SEQ * DMODEL];

// rope cos/sin table: [pos][freq] -> (cos, sin)
__device__ __align__(16) float2 g_ropetab[SEQ * 32];

// work-stealing counter (reset per launch)
__device__ int g_attn_work;

// ---------------------------------------------------------------------------
// Baseline-PTX helpers
// ---------------------------------------------------------------------------
__device__ __forceinline__ uint32_t smem_u32(const void* p) {
    uint32_t a;
    asm("{ .reg .u64 t; cvta.to.shared.u64 t, %1; cvt.u32.u64 %0, t; }"
        : "=r"(a) : "l"(p));
    return a;
}

__device__ __forceinline__ void cp16(uint32_t dst, const void* src) {
    asm volatile("cp.async.cg.shared.global [%0], [%1], 16;"
        :: "r"(dst), "l"(src) : "memory");
}
#define CP_COMMIT() asm volatile("cp.async.commit_group;" ::: "memory")
#define CP_WAIT1()  asm volatile("cp.async.wait_group 1;" ::: "memory")
#define CP_WAIT0()  asm volatile("cp.async.wait_group 0;" ::: "memory")

__device__ __forceinline__ void ldsm4(uint32_t r[4], uint32_t addr) {
    asm volatile("ldmatrix.sync.aligned.m8n8.x4.shared.b16 {%0,%1,%2,%3}, [%4];"
        : "=r"(r[0]), "=r"(r[1]), "=r"(r[2]), "=r"(r[3]) : "r"(addr));
}
__device__ __forceinline__ void ldsm4t(uint32_t r[4], uint32_t addr) {
    asm volatile("ldmatrix.sync.aligned.m8n8.x4.trans.shared.b16 {%0,%1,%2,%3}, [%4];"
        : "=r"(r[0]), "=r"(r[1]), "=r"(r[2]), "=r"(r[3]) : "r"(addr));
}

__device__ __forceinline__ void mma_f16(float c[4], const uint32_t a[4],
                                        uint32_t b0, uint32_t b1) {
    asm volatile(
        "mma.sync.aligned.m16n8k16.row.col.f32.f16.f16.f32 "
        "{%0,%1,%2,%3}, {%4,%5,%6,%7}, {%8,%9}, {%0,%1,%2,%3};"
        : "+f"(c[0]), "+f"(c[1]), "+f"(c[2]), "+f"(c[3])
        : "r"(a[0]), "r"(a[1]), "r"(a[2]), "r"(a[3]), "r"(b0), "r"(b1));
}

__device__ __forceinline__ uint32_t packh2(float a, float b) {
    __half2 h = __floats2half2_rn(a, b);
    return *(uint32_t*)&h;
}

__device__ __forceinline__ float ex2(float x) {
    float r;
    asm("ex2.approx.f32 %0, %1;" : "=f"(r) : "f"(x));
    return r;
}

// fp16 hi/lo split of a float pair: x = hi + lo + O(2^-21 |x|)
__device__ __forceinline__ void split2h(float a, float b, uint32_t& hi, uint32_t& lo) {
    __half ha = __float2half_rn(a);
    __half hb = __float2half_rn(b);
    __half2 hp(ha, hb);
    __half2 lp(__float2half_rn(a - __half2float(ha)),
               __float2half_rn(b - __half2float(hb)));
    hi = *(uint32_t*)&hp;
    lo = *(uint32_t*)&lp;
}

// ---------------------------------------------------------------------------
// rope table: angle(pos, i) = pos * 10000^(-i/32)
// ---------------------------------------------------------------------------
__global__ void rope_table()
{
    int idx = blockIdx.x * blockDim.x + threadIdx.x;
    if (idx >= SEQ * 32) return;
    const int pos = idx >> 5;
    const int i   = idx & 31;
    const float c1 = -9.210340371976184f / 32.0f;   // -ln(10000)/32
    const float ang = (float)pos * expf((float)i * c1);
    float sn, cs;
    sincosf(ang, &sn, &cs);
    g_ropetab[idx] = make_float2(cs, sn);
}

// ---------------------------------------------------------------------------
// Convert inputs: x, Wq, Wk, Wv -> single fp16; Wo -> fp16 hi/lo.
// grid.y (8 slices of 256K float4): 0..3 -> x quarters, 4..6 -> Wq..Wv, 7 -> Wo
// ---------------------------------------------------------------------------
#define WQ4 (DMODEL * DMODEL / 4)

__global__ void split_all(const float* __restrict__ x,
                          const float* __restrict__ w0, const float* __restrict__ w1,
                          const float* __restrict__ w2, const float* __restrict__ w3,
                          __half* __restrict__ xf,
                          __half* __restrict__ wh, __half* __restrict__ wl)
{
    const int sel = blockIdx.y;
    int i = blockIdx.x * blockDim.x + threadIdx.x;
    if (i >= WQ4) return;

    if (sel < 4) {
        const float* src = x + (size_t)sel * WQ4 * 4;
        float4 v = ((const float4*)src)[i];
        ((uint2*)xf)[(size_t)sel * WQ4 + i] =
            make_uint2(packh2(v.x, v.y), packh2(v.z, v.w));
    } else if (sel < 7) {
        const float* src = (sel == 4) ? w0 : (sel == 5) ? w1 : w2;
        float4 v = ((const float4*)src)[i];
        ((uint2*)wh)[(size_t)(sel - 4) * WQ4 + i] =
            make_uint2(packh2(v.x, v.y), packh2(v.z, v.w));
    } else {
        float4 v = ((const float4*)w3)[i];
        uint32_t h0, l0, h1, l1;
        split2h(v.x, v.y, h0, l0);
        split2h(v.z, v.w, h1, l1);
        ((uint2*)wh)[3 * (size_t)WQ4 + i] = make_uint2(h0, h1);
        ((uint2*)wl)[i] = make_uint2(l0, l1);
    }
}

// ---------------------------------------------------------------------------
// GEMM tiling constants: 128x128 CTA tile, 4 warps (2x2), 64x64 warp tile,
// BK=32, double-buffered cp.async, fp32 accumulate.
// ---------------------------------------------------------------------------
#define BK 32
#define NT (DMODEL / BK)
#define TILE_B (128 * 64)           // 8 KB per operand tile
#define STAGE1_B (2 * TILE_B)       // A, B            = 16 KB (single-pass)
#define STAGE2_B (3 * TILE_B)       // A, Bh, Bl       = 24 KB (2-pass)

struct GemmCore {
    float acc[4][8][4];
    int r0, c0;
};

struct GemmIdx {
    uint32_t aoff, boff;
    int wm, wn;
};

__device__ __forceinline__ GemmIdx gemm_idx() {
    const int tid = threadIdx.x;
    const int wid = tid >> 5, lane = tid & 31;
    GemmIdx g;
    g.wm = wid & 1;
    g.wn = wid >> 1;
    const int arow = g.wm * 64 + (lane & 15);
    const int ac0  = lane >> 4;
    g.aoff = (uint32_t)arow * 64 + (uint32_t)((ac0 ^ ((arow >> 1) & 3)) * 16);
    const int brow = g.wn * 64 + ((lane >> 4) << 3) + (lane & 7);
    const int bc0  = (lane >> 3) & 1;
    g.boff = (uint32_t)brow * 64 + (uint32_t)((bc0 ^ ((brow >> 1) & 3)) * 16);
    return g;
}

// copy one 128x32 fp16 tile (512 16B chunks) into swizzled smem
__device__ __forceinline__ void copy_tile(uint32_t dst, const __half* base, int k0) {
    const int tid = threadIdx.x;
#pragma unroll
    for (int j = 0; j < 4; j++) {
        const int idx = j * 128 + tid;
        const int r = idx >> 2, c = idx & 3;
        const uint32_t pc = (uint32_t)(c ^ ((r >> 1) & 3));
        cp16(dst + (uint32_t)r * 64 + pc * 16,
             base + (size_t)r * DMODEL + k0 + c * 8);
    }
}

// ---- single-pass mainloop (A, B fp16) ----
__device__ __forceinline__ void gemm_mainloop1(
    const __half* __restrict__ A, const __half* __restrict__ B,
    int bm, int bn, char* smem, GemmCore& core)
{
    const int lane = threadIdx.x & 31;
    const uint32_t sbase = smem_u32(smem);
    const GemmIdx gi = gemm_idx();

    const __half* Abase = A + (size_t)bm * DMODEL;
    const __half* Bbase = B + (size_t)bn * DMODEL;

#pragma unroll
    for (int i = 0; i < 4; i++)
#pragma unroll
        for (int j = 0; j < 8; j++)
#pragma unroll
            for (int q = 0; q < 4; q++) core.acc[i][j][q] = 0.f;

    copy_tile(sbase, Abase, 0);
    copy_tile(sbase + TILE_B, Bbase, 0);
    CP_COMMIT();

    for (int kt = 0; kt < NT; kt++) {
        const int s = kt & 1;
        if (kt + 1 < NT) {
            const uint32_t stb = sbase + (s ^ 1) * STAGE1_B;
            copy_tile(stb, Abase, (kt + 1) * BK);
            copy_tile(stb + TILE_B, Bbase, (kt + 1) * BK);
            CP_COMMIT();
            CP_WAIT1();
        } else {
            CP_WAIT0();
        }
        __syncthreads();

        const uint32_t stb = sbase + s * STAGE1_B;
        const uint32_t sA  = stb + gi.aoff;
        const uint32_t sB  = stb + TILE_B + gi.boff;

#pragma unroll
        for (int ks = 0; ks < 2; ks++) {
            const uint32_t kx = (uint32_t)(ks << 5);
            uint32_t af[4][4], bf[4][4];
#pragma unroll
            for (int mf = 0; mf < 4; mf++)
                ldsm4(af[mf], (sA + mf * 1024) ^ kx);
#pragma unroll
            for (int np = 0; np < 4; np++)
                ldsm4(bf[np], (sB + np * 1024) ^ kx);
#pragma unroll
            for (int mf = 0; mf < 4; mf++) {
#pragma unroll
                for (int nt = 0; nt < 8; nt++) {
                    const int np = nt >> 1, hh = (nt & 1) * 2;
                    mma_f16(core.acc[mf][nt], af[mf], bf[np][hh], bf[np][hh + 1]);
                }
            }
        }
        __syncthreads();
    }

    core.r0 = bm + gi.wm * 64 + (lane >> 2);
    core.c0 = bn + gi.wn * 64 + (lane & 3) * 2;
}

// ---- 2-pass mainloop (A fp16, B = Bh + Bl) for Wo ----
__device__ __forceinline__ void gemm_mainloop2(
    const __half* __restrict__ A,
    const __half* __restrict__ Bh, const __half* __restrict__ Bl,
    int bm, int bn, char* smem, GemmCore& core)
{
    const int lane = threadIdx.x & 31;
    const uint32_t sbase = smem_u32(smem);
    const GemmIdx gi = gemm_idx();

    const __half* Abase  = A  + (size_t)bm * DMODEL;
    const __half* Bhbase = Bh + (size_t)bn * DMODEL;
    const __half* Blbase = Bl + (size_t)bn * DMODEL;

#pragma unroll
    for (int i = 0; i < 4; i++)
#pragma unroll
        for (int j = 0; j < 8; j++)
#pragma unroll
            for (int q = 0; q < 4; q++) core.acc[i][j][q] = 0.f;

    copy_tile(sbase, Abase, 0);
    copy_tile(sbase + TILE_B, Bhbase, 0);
    copy_tile(sbase + 2 * TILE_B, Blbase, 0);
    CP_COMMIT();

    for (int kt = 0; kt < NT; kt++) {
        const int s = kt & 1;
        if (kt + 1 < NT) {
            const uint32_t stb = sbase + (s ^ 1) * STAGE2_B;
            copy_tile(stb, Abase, (kt + 1) * BK);
            copy_tile(stb + TILE_B, Bhbase, (kt + 1) * BK);
            copy_tile(stb + 2 * TILE_B, Blbase, (kt + 1) * BK);
            CP_COMMIT();
            CP_WAIT1();
        } else {
            CP_WAIT0();
        }
        __syncthreads();

        const uint32_t stb = sbase + s * STAGE2_B;
        const uint32_t sA  = stb + gi.aoff;
        const uint32_t sBh = stb + TILE_B + gi.boff;
        const uint32_t sBl = stb + 2 * TILE_B + gi.boff;

#pragma unroll
        for (int ks = 0; ks < 2; ks++) {
            const uint32_t kx = (uint32_t)(ks << 5);
            uint32_t af[4][4], bh[4][4], bl[4][4];
#pragma unroll
            for (int mf = 0; mf < 4; mf++)
                ldsm4(af[mf], (sA + mf * 1024) ^ kx);
#pragma unroll
            for (int np = 0; np < 4; np++) {
                ldsm4(bh[np], (sBh + np * 1024) ^ kx);
                ldsm4(bl[np], (sBl + np * 1024) ^ kx);
            }
#pragma unroll
            for (int mf = 0; mf < 4; mf++) {
#pragma unroll
                for (int nt = 0; nt < 8; nt++) {
                    const int np = nt >> 1, hh = (nt & 1) * 2;
                    mma_f16(core.acc[mf][nt], af[mf], bh[np][hh], bh[np][hh + 1]);
                    mma_f16(core.acc[mf][nt], af[mf], bl[np][hh], bl[np][hh + 1]);
                }
            }
        }
        __syncthreads();
    }

    core.r0 = bm + gi.wm * 64 + (lane >> 2);
    core.c0 = bn + gi.wn * 64 + (lane & 3) * 2;
}

// Fused QKV projection (single-pass fp16 GEMM).
// z=0: rope + scale*log2e -> Qf; z=1: rope -> Kf; z=2: pack -> Vf.
#define QSCALE 0.18033688011112042f   // 0.125 * log2(e)

__global__ __launch_bounds__(128, 2) void gemm_qkv(
    const __half* __restrict__ Xf, const __half* __restrict__ Wh,
    __half* __restrict__ Qf, __half* __restrict__ Kf, __half* __restrict__ Vf)
{
    extern __shared__ __align__(1024) char smem[];
    const int z = blockIdx.z;

    GemmCore core;
    gemm_mainloop1(Xf, Wh + (size_t)z * DMODEL * DMODEL,
                   blockIdx.y * 128, blockIdx.x * 128, smem, core);

    if (z == 2) {
#pragma unroll
        for (int mf = 0; mf < 4; mf++) {
#pragma unroll
            for (int nt = 0; nt < 8; nt++) {
                const size_t o0 = (size_t)(core.r0 + mf * 16) * DMODEL + core.c0 + nt * 8;
                const size_t o1 = (size_t)(core.r0 + mf * 16 + 8) * DMODEL + core.c0 + nt * 8;
                *(uint32_t*)&Vf[o0] = packh2(core.acc[mf][nt][0], core.acc[mf][nt][1]);
                *(uint32_t*)&Vf[o1] = packh2(core.acc[mf][nt][2], core.acc[mf][nt][3]);
            }
        }
    } else {
        __half* Dst = (z == 0) ? Qf : Kf;
        const float scale = (z == 0) ? QSCALE : 1.0f;
#pragma unroll
        for (int nt = 0; nt < 8; nt++) {
            const int col  = core.c0 + nt * 8;
            const int freq = (col & 63) >> 1;
#pragma unroll
            for (int mf = 0; mf < 4; mf++) {
                const int row0 = core.r0 + mf * 16;
                float2 t0 = g_ropetab[row0 * 32 + freq];
                float x1 = core.acc[mf][nt][0], x2 = core.acc[mf][nt][1];
                const size_t o0 = (size_t)row0 * DMODEL + col;
                *(uint32_t*)&Dst[o0] = packh2((x1 * t0.x - x2 * t0.y) * scale,
                                              (x1 * t0.y + x2 * t0.x) * scale);

                const int row1 = row0 + 8;
                float2 t1 = g_ropetab[row1 * 32 + freq];
                x1 = core.acc[mf][nt][2]; x2 = core.acc[mf][nt][3];
                const size_t o1 = (size_t)row1 * DMODEL + col;
                *(uint32_t*)&Dst[o1] = packh2((x1 * t1.x - x2 * t1.y) * scale,
                                              (x1 * t1.y + x2 * t1.x) * scale);
            }
        }
    }
}

// Output projection: ctx (fp16) x Wo (fp16 hi/lo), fp32 out.
__global__ __launch_bounds__(128, 2) void gemm_tc(
    const __half* __restrict__ A,
    const __half* __restrict__ Bh, const __half* __restrict__ Bl,
    float* __restrict__ C)
{
    extern __shared__ __align__(1024) char smem[];
    GemmCore core;
    gemm_mainloop2(A, Bh, Bl, blockIdx.y * 128, blockIdx.x * 128, smem, core);
#pragma unroll
    for (int mf = 0; mf < 4; mf++) {
#pragma unroll
        for (int nt = 0; nt < 8; nt++) {
            float* p0 = &C[(size_t)(core.r0 + mf * 16) * DMODEL + core.c0 + nt * 8];
            float* p1 = &C[(size_t)(core.r0 + mf * 16 + 8) * DMODEL + core.c0 + nt * 8];
            *(float2*)p0 = make_float2(core.acc[mf][nt][0], core.acc[mf][nt][1]);
            *(float2*)p1 = make_float2(core.acc[mf][nt][2], core.acc[mf][nt][3]);
        }
    }
}

// ---------------------------------------------------------------------------
// PERSISTENT tensor-core causal flash attention, all-fp16 single-pass.
// Q pre-scaled by 0.125*log2(e) -> scores in log2 domain, exp = ex2 (1 MUFU).
// ---------------------------------------------------------------------------
#define ATT_TILE_B 8192
#define ATT_STAGE_B (2 * ATT_TILE_B)         // Kf, Vf = 16 KB
#define ATT_SMEM (16384 + 2 * ATT_STAGE_B)   // 48 KB
#define ATT_UNITS (32 * NHEAD)               // 512
#define ATT_CTAS 444                         // 3 per SM x 148 SMs

__global__ __launch_bounds__(128, 3) void attn_tc(
    const __half* __restrict__ Qf, const __half* __restrict__ Kf,
    const __half* __restrict__ Vf, __half* __restrict__ Cf)
{
    extern __shared__ __align__(1024) char smem[];
    __shared__ int s_unit;
    const uint32_t sb = smem_u32(smem);
    const uint32_t qfb = sb;
    const uint32_t stgb = sb + 16384;

    const int tid  = threadIdx.x;
    const int wid  = tid >> 5, lane = tid & 31;

    const uint32_t lx = (uint32_t)(lane & 7);
    uint32_t qoff[4], koff[4], voff[4];
#pragma unroll
    for (int ks = 0; ks < 4; ks++) {
        qoff[ks] = (uint32_t)(lane & 15) * 128 +
                   ((uint32_t)(ks * 2 + (lane >> 4)) ^ lx) * 16;
        koff[ks] = (uint32_t)(((lane >> 4) << 3) + (lane & 7)) * 128 +
                   ((uint32_t)(ks * 2 + ((lane >> 3) & 1)) ^ lx) * 16;
        voff[ks] = (uint32_t)(lane & 15) * 128 +
                   ((uint32_t)(ks * 2 + (lane >> 4)) ^ lx) * 16;
    }

    for (;;) {
        __syncthreads();
        if (tid == 0) s_unit = atomicAdd(&g_attn_work, 1);
        __syncthreads();
        const int u = s_unit;
        if (u >= ATT_UNITS) break;

        const int qtile = 31 - (u >> 4);     // LPT: largest tiles first
        const int h     = u & 15;
        const int hcol  = h * DK;
        const int q0 = qtile * 128;
        const int ntiles = qtile * 2 + 2;

#pragma unroll
        for (int j = 0; j < 8; j++) {
            const int idx = j * 128 + tid;
            const int r = idx >> 3, c = idx & 7;
            const uint32_t off = (uint32_t)r * 128 + ((uint32_t)c ^ (uint32_t)(r & 7)) * 16;
            cp16(qfb + off, Qf + (size_t)(q0 + r) * DMODEL + hcol + c * 8);
        }
        CP_COMMIT();

        {
            const uint32_t stb = stgb;
#pragma unroll
            for (int j = 0; j < 4; j++) {
                const int idx = j * 128 + tid;
                const int r = idx >> 3, c = idx & 7;
                const uint32_t off = (uint32_t)r * 128 + ((uint32_t)c ^ (uint32_t)(r & 7)) * 16;
                const size_t g = (size_t)r * DMODEL + hcol + c * 8;
                cp16(stb + off,              Kf + g);
                cp16(stb + ATT_TILE_B + off, Vf + g);
            }
        }
        CP_COMMIT();

        CP_WAIT1();
        __syncthreads();

        uint32_t qf[2][4][4];
        const uint32_t qrb = (uint32_t)(wid * 32) * 128;
#pragma unroll
        for (int mf = 0; mf < 2; mf++)
#pragma unroll
            for (int ks = 0; ks < 4; ks++)
                ldsm4(qf[mf][ks], qfb + qrb + mf * 2048 + qoff[ks]);

        float O[2][8][4];
#pragma unroll
        for (int mf = 0; mf < 2; mf++)
#pragma unroll
            for (int f = 0; f < 8; f++)
#pragma unroll
                for (int q = 0; q < 4; q++) O[mf][f][q] = 0.f;
        float l0[2] = {0.f, 0.f}, l1[2] = {0.f, 0.f};

        int r0g[2], r1g[2];
#pragma unroll
        for (int mf = 0; mf < 2; mf++) {
            r0g[mf] = q0 + wid * 32 + mf * 16 + (lane >> 2);
            r1g[mf] = r0g[mf] + 8;
        }
        const int wrow_min = q0 + wid * 32;
        const int wrow_max = wrow_min + 31;

        for (int t = 0; t < ntiles; t++) {
            const int s = t & 1;
            if (t + 1 < ntiles) {
                const uint32_t stb = stgb + (s ^ 1) * ATT_STAGE_B;
                const int kn0 = (t + 1) * 64;
#pragma unroll
                for (int j = 0; j < 4; j++) {
                    const int idx = j * 128 + tid;
                    const int r = idx >> 3, c = idx & 7;
                    const uint32_t off = (uint32_t)r * 128 + ((uint32_t)c ^ (uint32_t)(r & 7)) * 16;
                    const size_t g = (size_t)(kn0 + r) * DMODEL + hcol + c * 8;
                    cp16(stb + off,              Kf + g);
                    cp16(stb + ATT_TILE_B + off, Vf + g);
                }
                CP_COMMIT();
                CP_WAIT1();
            } else {
                CP_WAIT0();
            }
            __syncthreads();

            const int k0 = t * 64;
            if (wrow_max >= k0) {
                const bool nomask = (k0 + 63) <= wrow_min;
                const uint32_t stb = stgb + s * ATT_STAGE_B;

#pragma unroll
                for (int np = 0; np < 4; np++) {
                    if (k0 + np * 16 > wrow_max) continue;   // P would be exactly 0

                    float s8[2][8];
#pragma unroll
                    for (int mf = 0; mf < 2; mf++)
#pragma unroll
                        for (int e = 0; e < 8; e++) s8[mf][e] = 0.f;
#pragma unroll
                    for (int ks = 0; ks < 4; ks++) {
                        uint32_t kv[4];
                        ldsm4(kv, stb + (uint32_t)np * 2048 + koff[ks]);
#pragma unroll
                        for (int mf = 0; mf < 2; mf++) {
                            mma_f16(&s8[mf][0], qf[mf][ks], kv[0], kv[1]);
                            mma_f16(&s8[mf][4], qf[mf][ks], kv[2], kv[3]);
                        }
                    }

                    const int c0 = k0 + np * 16 + ((lane & 3) << 1);
                    uint32_t Pf[2][4];
#pragma unroll
                    for (int mf = 0; mf < 2; mf++) {
                        float p[8];
                        if (nomask) {
#pragma unroll
                            for (int e = 0; e < 8; e++) p[e] = ex2(s8[mf][e]);
                        } else {
                            p[0] = (c0     <= r0g[mf]) ? ex2(s8[mf][0]) : 0.f;
                            p[1] = (c0 + 1 <= r0g[mf]) ? ex2(s8[mf][1]) : 0.f;
                            p[2] = (c0     <= r1g[mf]) ? ex2(s8[mf][2]) : 0.f;
                            p[3] = (c0 + 1 <= r1g[mf]) ? ex2(s8[mf][3]) : 0.f;
                            p[4] = (c0 + 8 <= r0g[mf]) ? ex2(s8[mf][4]) : 0.f;
                            p[5] = (c0 + 9 <= r0g[mf]) ? ex2(s8[mf][5]) : 0.f;
                            p[6] = (c0 + 8 <= r1g[mf]) ? ex2(s8[mf][6]) : 0.f;
                            p[7] = (c0 + 9 <= r1g[mf]) ? ex2(s8[mf][7]) : 0.f;
                        }
                        l0[mf] += (p[0] + p[1]) + (p[4] + p[5]);
                        l1[mf] += (p[2] + p[3]) + (p[6] + p[7]);
                        Pf[mf][0] = packh2(p[0], p[1]);
                        Pf[mf][1] = packh2(p[2], p[3]);
                        Pf[mf][2] = packh2(p[4], p[5]);
                        Pf[mf][3] = packh2(p[6], p[7]);
                    }

#pragma unroll
                    for (int dn = 0; dn < 4; dn++) {
                        uint32_t v4[4];
                        ldsm4t(v4, stb + ATT_TILE_B + (uint32_t)np * 2048 + voff[dn]);
#pragma unroll
                        for (int mf = 0; mf < 2; mf++) {
                            mma_f16(O[mf][dn * 2],     Pf[mf], v4[0], v4[1]);
                            mma_f16(O[mf][dn * 2 + 1], Pf[mf], v4[2], v4[3]);
                        }
                    }
                }
            }
            __syncthreads();
        }

        const int cbase = hcol + ((lane & 3) << 1);
#pragma unroll
        for (int mf = 0; mf < 2; mf++) {
            float a0 = l0[mf], a1 = l1[mf];
            a0 += __shfl_xor_sync(0xFFFFFFFF, a0, 1);
            a0 += __shfl_xor_sync(0xFFFFFFFF, a0, 2);
            a1 += __shfl_xor_sync(0xFFFFFFFF, a1, 1);
            a1 += __shfl_xor_sync(0xFFFFFFFF, a1, 2);
            const float inv0 = 1.f / a0, inv1 = 1.f / a1;
#pragma unroll
            for (int f = 0; f < 8; f++) {
                const size_t o0 = (size_t)r0g[mf] * DMODEL + cbase + f * 8;
                const size_t o1 = (size_t)r1g[mf] * DMODEL + cbase + f * 8;
                *(uint32_t*)&Cf[o0] = packh2(O[mf][f][0] * inv0, O[mf][f][1] * inv0);
                *(uint32_t*)&Cf[o1] = packh2(O[mf][f][2] * inv1, O[mf][f][3] * inv1);
            }
        }
    }
}

// ---------------------------------------------------------------------------
extern "C" void kernel_launch(void* const* d_in, const int* in_sizes, int n_in,
                              void* d_out, int out_size)
{
    const float* x  = (const float*)d_in[0];
    const float* Wq = (const float*)d_in[1];
    const float* Wk = (const float*)d_in[2];
    const float* Wv = (const float*)d_in[3];
    const float* Wo = (const float*)d_in[4];
    float* out = (float*)d_out;

    __half *xf, *wh, *wl, *cf, *qf, *kf, *vf;
    cudaGetSymbolAddress((void**)&xf, g_xf16);
    cudaGetSymbolAddress((void**)&wh, g_wh);
    cudaGetSymbolAddress((void**)&wl, g_wl);
    cudaGetSymbolAddress((void**)&cf, g_cf16);
    cudaGetSymbolAddress((void**)&qf, g_qf16);
    cudaGetSymbolAddress((void**)&kf, g_kf16);
    cudaGetSymbolAddress((void**)&vf, g_vf16);

    int* workp;
    cudaGetSymbolAddress((void**)&workp, g_attn_work);

    const int WSZ = DMODEL * DMODEL;

    static int attr_set = 0;
    if (!attr_set) {
        cudaFuncSetAttribute(gemm_qkv, cudaFuncAttributeMaxDynamicSharedMemorySize,
                             2 * STAGE1_B);
        cudaFuncSetAttribute(gemm_tc, cudaFuncAttributeMaxDynamicSharedMemorySize,
                             2 * STAGE2_B);
        cudaFuncSetAttribute(attn_tc, cudaFuncAttributeMaxDynamicSharedMemorySize,
                             ATT_SMEM);
        attr_set = 1;
    }

    cudaMemsetAsync(workp, 0, sizeof(int));

    rope_table<<<(SEQ * 32 + 255) / 256, 256>>>();
    split_all<<<dim3((WQ4 + 255) / 256, 8), 256>>>(x, Wq, Wk, Wv, Wo, xf, wh, wl);

    gemm_qkv<<<dim3(DMODEL / 128, SEQ / 128, 3), 128, 2 * STAGE1_B>>>(
        xf, wh, qf, kf, vf);

    attn_tc<<<ATT_CTAS, 128, ATT_SMEM>>>(qf, kf, vf, cf);

    gemm_tc<<<dim3(DMODEL / 128, SEQ / 128), 128, 2 * STAGE2_B>>>(
        cf, wh + 3 * (size_t)WSZ, wl, out);
}